// round 1
// baseline (speedup 1.0000x reference)
#include <cuda_runtime.h>

// ---------------- problem constants ----------------
#define NU 100000
#define NI 100000
#define FU 96
#define FI 160
#define HD 128
#define OD 64

// ---------------- scratch (device globals; no allocation allowed) ----------------
__device__ float g_hu   [NU * HD];
__device__ float g_hi   [NI * HD];
__device__ float g_agg_u[NU * HD];
__device__ float g_agg_i[NI * HD];
__device__ float g_hu1  [NU * HD];
__device__ float g_hi1  [NI * HD];
__device__ float g_aui  [NU * OD];   // h_u1 @ Wl1_ui (projected before aggregation)
__device__ float g_aiu  [NI * OD];   // h_i1 @ Wl1_iu
__device__ float g_agg64_u[NU * OD];
__device__ float g_agg64_i[NI * OD];
__device__ int   g_cnt_u[NU];
__device__ int   g_cnt_i[NI];
__device__ float g_inv_u[NU];
__device__ float g_inv_i[NI];

// ---------------- small kernels ----------------
__global__ void count_kernel(const int* __restrict__ dst, int E, int* __restrict__ cnt) {
    int e = blockIdx.x * blockDim.x + threadIdx.x;
    if (e < E) atomicAdd(&cnt[dst[e]], 1);
}

__global__ void inv_kernel(const int* __restrict__ cnt, int n, float* __restrict__ inv) {
    int i = blockIdx.x * blockDim.x + threadIdx.x;
    if (i < n) inv[i] = 1.0f / fmaxf((float)cnt[i], 1.0f);
}

// scatter-add src features into dst rows; one thread = 4 floats of one edge
template <int C>
__global__ void scatter_add_kernel(const float* __restrict__ feat,
                                   const int* __restrict__ edge, int E,
                                   float* __restrict__ agg) {
    constexpr int C4 = C / 4;
    int idx = blockIdx.x * blockDim.x + threadIdx.x;
    if (idx >= E * C4) return;
    int e = idx / C4;
    int c = (idx & (C4 - 1)) * 4;
    int s = edge[e];
    int d = edge[E + e];
    float4 v = *(const float4*)(feat + (long)s * C + c);
    float* p = agg + (long)d * C + c;
    atomicAdd(p + 0, v.x);
    atomicAdd(p + 1, v.y);
    atomicAdd(p + 2, v.z);
    atomicAdd(p + 3, v.w);
}

template <int C, int SHIFT>
__global__ void scale_rows_kernel(float* __restrict__ a, const float* __restrict__ inv, int n) {
    int idx = blockIdx.x * blockDim.x + threadIdx.x;
    if (idx < n * C) a[idx] *= __ldg(&inv[idx >> SHIFT]);
}

// ---------------- fused GEMM ----------------
// out[M,BN] = post( A1[M,K1]@W1[K1,BN] (+ A2[M,K2]@W2[K2,BN]) (+ D) (+ bias) )
// post = optional LayerNorm (gamma,beta) then optional ReLU.
// BM=64, BK=16, 256 threads. Warp ty owns 8 rows; lane tx owns TN=BN/32 cols -> LN via warp shuffles.
#define BM 64
#define BK 16

template <int BN, bool FUSE2, bool HAS_D, bool DO_LN, bool DO_RELU>
__global__ __launch_bounds__(256)
void gemm_kernel(const float* __restrict__ A1, const float* __restrict__ W1, int K1,
                 const float* __restrict__ A2, const float* __restrict__ W2, int K2,
                 const float* __restrict__ D, const float* __restrict__ bias,
                 const float* __restrict__ gamma, const float* __restrict__ beta,
                 float* __restrict__ out, int M) {
    constexpr int TN = BN / 32;
    __shared__ float As[BK][BM];
    __shared__ float Ws[BK][BN];

    const int tid = threadIdx.x;
    const int tx = tid & 31;
    const int ty = tid >> 5;
    const int r0 = blockIdx.x * BM;

    float acc[8][TN];
#pragma unroll
    for (int i = 0; i < 8; i++)
#pragma unroll
        for (int j = 0; j < TN; j++) acc[i][j] = 0.0f;

    const int la_row = tid & 63;
    const int la_k = (tid >> 6) * 4;
    const int grow = r0 + la_row;
    const int Ktot = FUSE2 ? (K1 + K2) : K1;

    for (int k0 = 0; k0 < Ktot; k0 += BK) {
        const float* A;
        const float* W;
        int kk0, K;
        if (FUSE2 && k0 >= K1) { A = A2; W = W2; kk0 = k0 - K1; K = K2; }
        else                   { A = A1; W = W1; kk0 = k0;      K = K1; }

        float4 av = make_float4(0.f, 0.f, 0.f, 0.f);
        if (grow < M) av = *(const float4*)(A + (long)grow * K + kk0 + la_k);
        As[la_k + 0][la_row] = av.x;
        As[la_k + 1][la_row] = av.y;
        As[la_k + 2][la_row] = av.z;
        As[la_k + 3][la_row] = av.w;

        constexpr int WV = BK * BN / 4;  // 512 (BN=128) or 256 (BN=64)
#pragma unroll
        for (int i = tid; i < WV; i += 256) {
            int wr = i / (BN / 4);
            int wc = (i % (BN / 4)) * 4;
            *(float4*)&Ws[wr][wc] = *(const float4*)(W + (long)(kk0 + wr) * BN + wc);
        }
        __syncthreads();

#pragma unroll
        for (int kk = 0; kk < BK; kk++) {
            float b[TN];
#pragma unroll
            for (int j = 0; j < TN; j++) b[j] = Ws[kk][tx * TN + j];
#pragma unroll
            for (int i = 0; i < 8; i++) {
                float a = As[kk][ty * 8 + i];
#pragma unroll
                for (int j = 0; j < TN; j++) acc[i][j] = fmaf(a, b[j], acc[i][j]);
            }
        }
        __syncthreads();
    }

    // epilogue
    const int cbase = tx * TN;
    float bia[TN];
#pragma unroll
    for (int j = 0; j < TN; j++) bia[j] = bias ? bias[cbase + j] : 0.0f;
    float gm[TN], bt[TN];
    if (DO_LN) {
#pragma unroll
        for (int j = 0; j < TN; j++) { gm[j] = gamma[cbase + j]; bt[j] = beta[cbase + j]; }
    }

#pragma unroll
    for (int i = 0; i < 8; i++) {
        int r = r0 + ty * 8 + i;
        bool ok = (r < M);
        float v[TN];
#pragma unroll
        for (int j = 0; j < TN; j++) v[j] = acc[i][j] + bia[j];
        if (HAS_D) {
            if (ok) {
#pragma unroll
                for (int j = 0; j < TN; j++) v[j] += __ldg(&D[(long)r * BN + cbase + j]);
            }
        }
        if (DO_LN) {
            float s1 = 0.f, s2 = 0.f;
#pragma unroll
            for (int j = 0; j < TN; j++) { s1 += v[j]; s2 += v[j] * v[j]; }
#pragma unroll
            for (int o = 16; o > 0; o >>= 1) {
                s1 += __shfl_xor_sync(0xFFFFFFFFu, s1, o);
                s2 += __shfl_xor_sync(0xFFFFFFFFu, s2, o);
            }
            float mean = s1 * (1.0f / BN);
            float var = s2 * (1.0f / BN) - mean * mean;
            float rstd = rsqrtf(var + 1e-5f);
#pragma unroll
            for (int j = 0; j < TN; j++) v[j] = (v[j] - mean) * rstd * gm[j] + bt[j];
        }
        if (DO_RELU) {
#pragma unroll
            for (int j = 0; j < TN; j++) v[j] = fmaxf(v[j], 0.0f);
        }
        if (ok) {
            if (TN == 4) {
                *(float4*)(out + (long)r * BN + cbase) = make_float4(v[0], v[1], v[2], v[3]);
            } else {
                *(float2*)(out + (long)r * BN + cbase) = make_float2(v[0], v[1]);
            }
        }
    }
}

// ---------------- host launcher ----------------
extern "C" void kernel_launch(void* const* d_in, const int* in_sizes, int n_in,
                              void* d_out, int out_size) {
    const float* x_user = (const float*)d_in[0];
    const float* x_item = (const float*)d_in[1];
    const int* edge_ui = (const int*)d_in[2];
    const int* edge_iu = (const int*)d_in[3];
    const float* Wp_u = (const float*)d_in[4];
    const float* bp_u = (const float*)d_in[5];
    const float* Wp_i = (const float*)d_in[6];
    const float* bp_i = (const float*)d_in[7];
    const float* Wl0_ui = (const float*)d_in[8];
    const float* bl0_ui = (const float*)d_in[9];
    const float* Wr0_ui = (const float*)d_in[10];
    const float* Wl0_iu = (const float*)d_in[11];
    const float* bl0_iu = (const float*)d_in[12];
    const float* Wr0_iu = (const float*)d_in[13];
    const float* g0_u = (const float*)d_in[14];
    const float* b0_u = (const float*)d_in[15];
    const float* g0_i = (const float*)d_in[16];
    const float* b0_i = (const float*)d_in[17];
    const float* Wl1_ui = (const float*)d_in[18];
    const float* bl1_ui = (const float*)d_in[19];
    const float* Wr1_ui = (const float*)d_in[20];
    const float* Wl1_iu = (const float*)d_in[21];
    const float* bl1_iu = (const float*)d_in[22];
    const float* Wr1_iu = (const float*)d_in[23];
    const float* g1_u = (const float*)d_in[24];
    const float* b1_u = (const float*)d_in[25];
    const float* g1_i = (const float*)d_in[26];
    const float* b1_i = (const float*)d_in[27];

    const int E = in_sizes[2] / 2;

    float *hu, *hi, *agg_u, *agg_i, *hu1, *hi1, *aui, *aiu, *a64u, *a64i, *inv_u, *inv_i;
    int *cnt_u, *cnt_i;
    cudaGetSymbolAddress((void**)&hu, g_hu);
    cudaGetSymbolAddress((void**)&hi, g_hi);
    cudaGetSymbolAddress((void**)&agg_u, g_agg_u);
    cudaGetSymbolAddress((void**)&agg_i, g_agg_i);
    cudaGetSymbolAddress((void**)&hu1, g_hu1);
    cudaGetSymbolAddress((void**)&hi1, g_hi1);
    cudaGetSymbolAddress((void**)&aui, g_aui);
    cudaGetSymbolAddress((void**)&aiu, g_aiu);
    cudaGetSymbolAddress((void**)&a64u, g_agg64_u);
    cudaGetSymbolAddress((void**)&a64i, g_agg64_i);
    cudaGetSymbolAddress((void**)&cnt_u, g_cnt_u);
    cudaGetSymbolAddress((void**)&cnt_i, g_cnt_i);
    cudaGetSymbolAddress((void**)&inv_u, g_inv_u);
    cudaGetSymbolAddress((void**)&inv_i, g_inv_i);

    float* out_u = (float*)d_out;             // h_u2 first
    float* out_i = (float*)d_out + (long)NU * OD;  // then h_i2

    // zero accumulators (memset nodes are graph-capturable)
    cudaMemsetAsync(agg_u, 0, (size_t)NU * HD * sizeof(float));
    cudaMemsetAsync(agg_i, 0, (size_t)NI * HD * sizeof(float));
    cudaMemsetAsync(a64u, 0, (size_t)NU * OD * sizeof(float));
    cudaMemsetAsync(a64i, 0, (size_t)NI * OD * sizeof(float));
    cudaMemsetAsync(cnt_u, 0, (size_t)NU * sizeof(int));
    cudaMemsetAsync(cnt_i, 0, (size_t)NI * sizeof(int));

    const int gmU = (NU + BM - 1) / BM;
    const int gmI = (NI + BM - 1) / BM;

    // input projection + ReLU
    gemm_kernel<HD, false, false, false, true><<<gmU, 256>>>(
        x_user, Wp_u, FU, nullptr, nullptr, 0, nullptr, bp_u, nullptr, nullptr, hu, NU);
    gemm_kernel<HD, false, false, false, true><<<gmI, 256>>>(
        x_item, Wp_i, FI, nullptr, nullptr, 0, nullptr, bp_i, nullptr, nullptr, hi, NI);

    // degree counts + reciprocals
    count_kernel<<<(E + 255) / 256, 256>>>(edge_ui + E, E, cnt_i);
    count_kernel<<<(E + 255) / 256, 256>>>(edge_iu + E, E, cnt_u);
    inv_kernel<<<(NI + 255) / 256, 256>>>(cnt_i, NI, inv_i);
    inv_kernel<<<(NU + 255) / 256, 256>>>(cnt_u, NU, inv_u);

    // layer 0 aggregation (C=128)
    {
        int total = E * (HD / 4);
        scatter_add_kernel<HD><<<(total + 255) / 256, 256>>>(hu, edge_ui, E, agg_i);
        scatter_add_kernel<HD><<<(total + 255) / 256, 256>>>(hi, edge_iu, E, agg_u);
    }
    scale_rows_kernel<HD, 7><<<(NI * HD + 255) / 256, 256>>>(agg_i, inv_i, NI);
    scale_rows_kernel<HD, 7><<<(NU * HD + 255) / 256, 256>>>(agg_u, inv_u, NU);

    // layer 0: fused dual-GEMM + bias + LN + ReLU
    gemm_kernel<HD, true, false, true, true><<<gmI, 256>>>(
        agg_i, Wl0_ui, HD, hi, Wr0_ui, HD, nullptr, bl0_ui, g0_i, b0_i, hi1, NI);
    gemm_kernel<HD, true, false, true, true><<<gmU, 256>>>(
        agg_u, Wl0_iu, HD, hu, Wr0_iu, HD, nullptr, bl0_iu, g0_u, b0_u, hu1, NU);

    // layer 1: project sources first (mean is linear) -> halves scatter width
    gemm_kernel<OD, false, false, false, false><<<gmU, 256>>>(
        hu1, Wl1_ui, HD, nullptr, nullptr, 0, nullptr, nullptr, nullptr, nullptr, aui, NU);
    gemm_kernel<OD, false, false, false, false><<<gmI, 256>>>(
        hi1, Wl1_iu, HD, nullptr, nullptr, 0, nullptr, nullptr, nullptr, nullptr, aiu, NI);

    {
        int total = E * (OD / 4);
        scatter_add_kernel<OD><<<(total + 255) / 256, 256>>>(aui, edge_ui, E, a64i);
        scatter_add_kernel<OD><<<(total + 255) / 256, 256>>>(aiu, edge_iu, E, a64u);
    }
    scale_rows_kernel<OD, 6><<<(NI * OD + 255) / 256, 256>>>(a64i, inv_i, NI);
    scale_rows_kernel<OD, 6><<<(NU * OD + 255) / 256, 256>>>(a64u, inv_u, NU);

    // layer 1 final: root GEMM + aggregated term + bias + LN (no ReLU)
    gemm_kernel<OD, false, true, true, false><<<gmU, 256>>>(
        hu1, Wr1_iu, HD, nullptr, nullptr, 0, a64u, bl1_iu, g1_u, b1_u, out_u, NU);
    gemm_kernel<OD, false, true, true, false><<<gmI, 256>>>(
        hi1, Wr1_ui, HD, nullptr, nullptr, 0, a64i, bl1_ui, g1_i, b1_i, out_i, NI);

    (void)n_in; (void)out_size; (void)in_sizes;
}

// round 3
// speedup vs baseline: 2.5098x; 2.5098x over previous
#include <cuda_runtime.h>
#include <cuda_bf16.h>
#include <cstdint>

// ---------------- problem constants ----------------
#define NU 100000
#define NI 100000
#define FU 96
#define FI 160
#define HD 128
#define OD 64

// ---------------- scratch (device globals) ----------------
__device__ float g_hu   [NU * HD];
__device__ float g_hi   [NI * HD];
__device__ float g_agg_u[NU * HD];
__device__ float g_agg_i[NI * HD];
__device__ float g_hu1  [NU * HD];
__device__ float g_hi1  [NI * HD];
__device__ float g_aui  [NU * OD];
__device__ float g_aiu  [NI * OD];
__device__ float g_agg64_u[NU * OD];
__device__ float g_agg64_i[NI * OD];
__device__ int   g_cnt_u[NU];
__device__ int   g_cnt_i[NI];
__device__ float g_inv_u[NU];
__device__ float g_inv_i[NI];

// transposed/split bf16 weights: layout [N rows, Kpad cols], zero padded
__device__ __nv_bfloat16 g_wpu_h[128 * 128],  g_wpu_l[128 * 128];
__device__ __nv_bfloat16 g_wpi_h[128 * 192],  g_wpi_l[128 * 192];
__device__ __nv_bfloat16 g_wl0ui_h[128 * 128], g_wl0ui_l[128 * 128];
__device__ __nv_bfloat16 g_wr0ui_h[128 * 128], g_wr0ui_l[128 * 128];
__device__ __nv_bfloat16 g_wl0iu_h[128 * 128], g_wl0iu_l[128 * 128];
__device__ __nv_bfloat16 g_wr0iu_h[128 * 128], g_wr0iu_l[128 * 128];
__device__ __nv_bfloat16 g_wl1ui_h[64 * 128],  g_wl1ui_l[64 * 128];
__device__ __nv_bfloat16 g_wr1ui_h[64 * 128],  g_wr1ui_l[64 * 128];
__device__ __nv_bfloat16 g_wl1iu_h[64 * 128],  g_wl1iu_l[64 * 128];
__device__ __nv_bfloat16 g_wr1iu_h[64 * 128],  g_wr1iu_l[64 * 128];

// ---------------- helpers ----------------
__device__ __forceinline__ uint32_t smem_u32(const void* p) {
    uint32_t a;
    asm("{ .reg .u64 t; cvta.to.shared.u64 t, %1; cvt.u32.u64 %0, t; }" : "=r"(a) : "l"(p));
    return a;
}
#define SWZ(x) ((x) ^ (((x) >> 3) & 0x70))

__device__ __forceinline__ void ldm4(uint32_t* r, uint32_t addr) {
    asm volatile("ldmatrix.sync.aligned.m8n8.x4.shared.b16 {%0,%1,%2,%3}, [%4];"
        : "=r"(r[0]), "=r"(r[1]), "=r"(r[2]), "=r"(r[3]) : "r"(addr));
}
__device__ __forceinline__ void mma_bf16(float* c, const uint32_t* a, uint32_t b0, uint32_t b1) {
    asm volatile("mma.sync.aligned.m16n8k16.row.col.f32.bf16.bf16.f32 "
        "{%0,%1,%2,%3}, {%4,%5,%6,%7}, {%8,%9}, {%0,%1,%2,%3};"
        : "+f"(c[0]), "+f"(c[1]), "+f"(c[2]), "+f"(c[3])
        : "r"(a[0]), "r"(a[1]), "r"(a[2]), "r"(a[3]), "r"(b0), "r"(b1));
}

// ---------------- small kernels ----------------
__global__ void count_kernel(const int* __restrict__ dst, int E, int* __restrict__ cnt) {
    int e = blockIdx.x * blockDim.x + threadIdx.x;
    if (e < E) atomicAdd(&cnt[dst[e]], 1);
}
__global__ void inv_kernel(const int* __restrict__ cnt, int n, float* __restrict__ inv) {
    int i = blockIdx.x * blockDim.x + threadIdx.x;
    if (i < n) inv[i] = 1.0f / fmaxf((float)cnt[i], 1.0f);
}

template <int C>
__global__ void scatter_add_kernel(const float* __restrict__ feat,
                                   const int* __restrict__ edge, int E,
                                   float* __restrict__ agg) {
    constexpr int C4 = C / 4;
    int idx = blockIdx.x * blockDim.x + threadIdx.x;
    if (idx >= E * C4) return;
    int e = idx / C4;
    int c = (idx & (C4 - 1)) * 4;
    int s = edge[e];
    int d = edge[E + e];
    float4 v = *(const float4*)(feat + (size_t)s * C + c);
    float* p = agg + (size_t)d * C + c;
    asm volatile("red.global.add.v4.f32 [%0], {%1, %2, %3, %4};"
                 :: "l"(p), "f"(v.x), "f"(v.y), "f"(v.z), "f"(v.w) : "memory");
}

template <int C, int SHIFT>
__global__ void scale_rows_kernel(float* __restrict__ a, const float* __restrict__ inv, int n) {
    int idx = blockIdx.x * blockDim.x + threadIdx.x;
    if (idx < n * C) a[idx] *= __ldg(&inv[idx >> SHIFT]);
}

// weight transpose + bf16 hi/lo split: W [K,N] fp32 -> Wt [N,Kpad] bf16 (hi,lo), zero pad
struct WCon { const float* w; __nv_bfloat16* h; __nv_bfloat16* l; int K, N, Kpad; };
struct WCon10 { WCon s[10]; };
__global__ void wconv_kernel(WCon10 P) {
    WCon w = P.s[blockIdx.y];
    int idx = blockIdx.x * blockDim.x + threadIdx.x;
    if (idx >= w.N * w.Kpad) return;
    int n = idx / w.Kpad, k = idx % w.Kpad;
    float x = (k < w.K) ? w.w[(size_t)k * w.N + n] : 0.0f;
    __nv_bfloat16 h = __float2bfloat16(x);
    w.h[idx] = h;
    w.l[idx] = __float2bfloat16(x - __bfloat162float(h));
}

// ---------------- HMMA (mma.sync) GEMM ----------------
// out[M,BN] = post( A1[M,K1]@W1 (+ A2@W2) (+ Dext) (+ bias) ), post = opt LN then opt ReLU.
// 3-pass bf16 split (hi*hi + hi*lo + lo*hi), fp32 accum in registers.
// Block: 128 rows, 8 warps, warp = 16 rows x BN cols (LN intra-warp over quads).
// SMEM tiles: A 128x64 bf16 hi/lo (SW128), B BNx64 bf16 hi/lo; single buffered, chunk K=64.

template <int BN, bool FUSE2, bool HAS_D, bool DO_LN, bool DO_RELU>
__global__ __launch_bounds__(256, 2)
void mma_gemm(const float* __restrict__ A1, const __nv_bfloat16* __restrict__ W1h, const __nv_bfloat16* __restrict__ W1l,
              int K1, int K1pad,
              const float* __restrict__ A2, const __nv_bfloat16* __restrict__ W2h, const __nv_bfloat16* __restrict__ W2l,
              int K2, int K2pad,
              const float* __restrict__ Dext, const float* __restrict__ bias,
              const float* __restrict__ gamma, const float* __restrict__ beta,
              float* __restrict__ out, int M) {
    static_assert(BN == 64 || BN == 128, "");
    constexpr int FN = BN / 8;

    extern __shared__ char smem[];
    const uint32_t sb = smem_u32(smem);
    const uint32_t aHiB = sb;
    const uint32_t aLoB = sb + 16384;
    const uint32_t bHiB = sb + 32768;
    const uint32_t bLoB = bHiB + BN * 128;

    const int tid = threadIdx.x;
    const int warp = tid >> 5;
    const int lane = tid & 31;
    const int r0 = blockIdx.x * 128;

    float acc[FN][4];
#pragma unroll
    for (int i = 0; i < FN; i++)
#pragma unroll
        for (int j = 0; j < 4; j++) acc[i][j] = 0.0f;

    // staging mapping
    const int ar = tid >> 1;
    const int acb = (tid & 1) * 32;
    constexpr int TPR = 256 / BN;
    constexpr int WNC = 64 / TPR;
    const int bn = tid / TPR;
    const int bq = tid % TPR;

    // compute-phase lane constants
    const uint32_t a_row = warp * 16 + (lane & 15);
    const uint32_t a_rowoff = a_row * 128;
    const uint32_t a_xm = (a_row & 7) * 16;
    const uint32_t a_khalf = ((lane >> 4) & 1) * 16;
    const uint32_t b_rowbase = ((lane & 7) + ((lane >> 4) & 1) * 8) * 128;
    const uint32_t b_xm = (lane & 7) * 16;
    const uint32_t b_khalf = ((lane >> 3) & 1) * 16;

    const int nch1 = K1pad >> 6;
    const int nch = nch1 + (FUSE2 ? (K2pad >> 6) : 0);

    for (int c = 0; c < nch; c++) {
        if (c) __syncthreads();

        const float* A;
        const __nv_bfloat16 *Wh, *Wl;
        int k0, K, Kpad;
        if (!FUSE2 || c < nch1) { A = A1; Wh = W1h; Wl = W1l; k0 = c * 64; K = K1; Kpad = K1pad; }
        else                    { A = A2; Wh = W2h; Wl = W2l; k0 = (c - nch1) * 64; K = K2; Kpad = K2pad; }

        // ---- stage A (fp32 -> bf16 hi/lo, swizzled) ----
        {
            const int grow = r0 + ar;
            const float* arow = A + (size_t)grow * K;
#pragma unroll
            for (int i = 0; i < 4; i++) {
                const int cc = acb + i * 8;
                float x[8];
#pragma unroll
                for (int j = 0; j < 8; j++) x[j] = 0.0f;
                if (grow < M && (k0 + cc) < K) {
                    float4 v0 = *(const float4*)(arow + k0 + cc);
                    float4 v1 = *(const float4*)(arow + k0 + cc + 4);
                    x[0] = v0.x; x[1] = v0.y; x[2] = v0.z; x[3] = v0.w;
                    x[4] = v1.x; x[5] = v1.y; x[6] = v1.z; x[7] = v1.w;
                }
                uint32_t hi[4], lo[4];
#pragma unroll
                for (int j = 0; j < 4; j++) {
                    __nv_bfloat16 h0 = __float2bfloat16(x[2 * j]);
                    __nv_bfloat16 h1 = __float2bfloat16(x[2 * j + 1]);
                    float l0 = x[2 * j] - __bfloat162float(h0);
                    float l1 = x[2 * j + 1] - __bfloat162float(h1);
                    __nv_bfloat16 e0 = __float2bfloat16(l0);
                    __nv_bfloat16 e1 = __float2bfloat16(l1);
                    hi[j] = (uint32_t)__bfloat16_as_ushort(h0) | ((uint32_t)__bfloat16_as_ushort(h1) << 16);
                    lo[j] = (uint32_t)__bfloat16_as_ushort(e0) | ((uint32_t)__bfloat16_as_ushort(e1) << 16);
                }
                const uint32_t off = SWZ(ar * 128 + cc * 2);
                asm volatile("st.shared.v4.b32 [%0], {%1, %2, %3, %4};" :: "r"(aHiB + off), "r"(hi[0]), "r"(hi[1]), "r"(hi[2]), "r"(hi[3]) : "memory");
                asm volatile("st.shared.v4.b32 [%0], {%1, %2, %3, %4};" :: "r"(aLoB + off), "r"(lo[0]), "r"(lo[1]), "r"(lo[2]), "r"(lo[3]) : "memory");
            }
        }
        // ---- stage B (pre-split bf16 [BN, Kpad], swizzled copy) ----
        {
#pragma unroll
            for (int i = 0; i < WNC / 8; i++) {
                const int ck = bq * WNC + i * 8;
                const size_t so = (size_t)bn * Kpad + k0 + ck;
                uint4 vh = *(const uint4*)(Wh + so);
                uint4 vl = *(const uint4*)(Wl + so);
                const uint32_t off = SWZ(bn * 128 + ck * 2);
                asm volatile("st.shared.v4.b32 [%0], {%1, %2, %3, %4};" :: "r"(bHiB + off), "r"(vh.x), "r"(vh.y), "r"(vh.z), "r"(vh.w) : "memory");
                asm volatile("st.shared.v4.b32 [%0], {%1, %2, %3, %4};" :: "r"(bLoB + off), "r"(vl.x), "r"(vl.y), "r"(vl.z), "r"(vl.w) : "memory");
            }
        }
        __syncthreads();

        // ---- compute ----
#pragma unroll
        for (int ks = 0; ks < 4; ks++) {
            const uint32_t akb = ((uint32_t)(ks * 32) + a_khalf) ^ a_xm;
            uint32_t ah[4], al[4];
            ldm4(ah, aHiB + a_rowoff + akb);
            ldm4(al, aLoB + a_rowoff + akb);
            const uint32_t bkb = ((uint32_t)(ks * 32) + b_khalf) ^ b_xm;
#pragma unroll
            for (int j = 0; j < FN / 2; j++) {
                uint32_t bh[4], bl[4];
                const uint32_t boff = b_rowbase + (uint32_t)j * 2048;
                ldm4(bh, bHiB + boff + bkb);
                ldm4(bl, bLoB + boff + bkb);
                mma_bf16(acc[2 * j],     ah, bh[0], bh[1]);
                mma_bf16(acc[2 * j],     ah, bl[0], bl[1]);
                mma_bf16(acc[2 * j],     al, bh[0], bh[1]);
                mma_bf16(acc[2 * j + 1], ah, bh[2], bh[3]);
                mma_bf16(acc[2 * j + 1], ah, bl[2], bl[3]);
                mma_bf16(acc[2 * j + 1], al, bh[2], bh[3]);
            }
        }
    }

    // ---- epilogue ----
    const int row0 = r0 + warp * 16 + (lane >> 2);
    const int row1 = row0 + 8;
    const int cb = (lane & 3) * 2;

    if (bias) {
#pragma unroll
        for (int fn = 0; fn < FN; fn++) {
            float2 bv = __ldg((const float2*)(bias + fn * 8 + cb));
            acc[fn][0] += bv.x; acc[fn][1] += bv.y;
            acc[fn][2] += bv.x; acc[fn][3] += bv.y;
        }
    }
    if (HAS_D) {
        if (row0 < M) {
#pragma unroll
            for (int fn = 0; fn < FN; fn++) {
                float2 dv = __ldg((const float2*)(Dext + (size_t)row0 * BN + fn * 8 + cb));
                acc[fn][0] += dv.x; acc[fn][1] += dv.y;
            }
        }
        if (row1 < M) {
#pragma unroll
            for (int fn = 0; fn < FN; fn++) {
                float2 dv = __ldg((const float2*)(Dext + (size_t)row1 * BN + fn * 8 + cb));
                acc[fn][2] += dv.x; acc[fn][3] += dv.y;
            }
        }
    }
    if (DO_LN) {
        float s1a = 0.f, s2a = 0.f, s1b = 0.f, s2b = 0.f;
#pragma unroll
        for (int fn = 0; fn < FN; fn++) {
            s1a += acc[fn][0] + acc[fn][1];
            s2a += acc[fn][0] * acc[fn][0] + acc[fn][1] * acc[fn][1];
            s1b += acc[fn][2] + acc[fn][3];
            s2b += acc[fn][2] * acc[fn][2] + acc[fn][3] * acc[fn][3];
        }
#pragma unroll
        for (int o = 1; o < 4; o <<= 1) {
            s1a += __shfl_xor_sync(0xFFFFFFFFu, s1a, o);
            s2a += __shfl_xor_sync(0xFFFFFFFFu, s2a, o);
            s1b += __shfl_xor_sync(0xFFFFFFFFu, s1b, o);
            s2b += __shfl_xor_sync(0xFFFFFFFFu, s2b, o);
        }
        const float inv_n = 1.0f / BN;
        float ma = s1a * inv_n, mb = s1b * inv_n;
        float ra = rsqrtf(s2a * inv_n - ma * ma + 1e-5f);
        float rb = rsqrtf(s2b * inv_n - mb * mb + 1e-5f);
#pragma unroll
        for (int fn = 0; fn < FN; fn++) {
            float2 g = __ldg((const float2*)(gamma + fn * 8 + cb));
            float2 b = __ldg((const float2*)(beta + fn * 8 + cb));
            acc[fn][0] = (acc[fn][0] - ma) * ra * g.x + b.x;
            acc[fn][1] = (acc[fn][1] - ma) * ra * g.y + b.y;
            acc[fn][2] = (acc[fn][2] - mb) * rb * g.x + b.x;
            acc[fn][3] = (acc[fn][3] - mb) * rb * g.y + b.y;
        }
    }
    if (DO_RELU) {
#pragma unroll
        for (int fn = 0; fn < FN; fn++)
#pragma unroll
            for (int j = 0; j < 4; j++) acc[fn][j] = fmaxf(acc[fn][j], 0.0f);
    }
    if (row0 < M) {
#pragma unroll
        for (int fn = 0; fn < FN; fn++)
            *(float2*)(out + (size_t)row0 * BN + fn * 8 + cb) = make_float2(acc[fn][0], acc[fn][1]);
    }
    if (row1 < M) {
#pragma unroll
        for (int fn = 0; fn < FN; fn++)
            *(float2*)(out + (size_t)row1 * BN + fn * 8 + cb) = make_float2(acc[fn][2], acc[fn][3]);
    }
}

// ---------------- host launcher ----------------
extern "C" void kernel_launch(void* const* d_in, const int* in_sizes, int n_in,
                              void* d_out, int out_size) {
    const float* x_user = (const float*)d_in[0];
    const float* x_item = (const float*)d_in[1];
    const int* edge_ui = (const int*)d_in[2];
    const int* edge_iu = (const int*)d_in[3];
    const float* Wp_u = (const float*)d_in[4];
    const float* bp_u = (const float*)d_in[5];
    const float* Wp_i = (const float*)d_in[6];
    const float* bp_i = (const float*)d_in[7];
    const float* Wl0_ui = (const float*)d_in[8];
    const float* bl0_ui = (const float*)d_in[9];
    const float* Wr0_ui = (const float*)d_in[10];
    const float* Wl0_iu = (const float*)d_in[11];
    const float* bl0_iu = (const float*)d_in[12];
    const float* Wr0_iu = (const float*)d_in[13];
    const float* g0_u = (const float*)d_in[14];
    const float* b0_u = (const float*)d_in[15];
    const float* g0_i = (const float*)d_in[16];
    const float* b0_i = (const float*)d_in[17];
    const float* Wl1_ui = (const float*)d_in[18];
    const float* bl1_ui = (const float*)d_in[19];
    const float* Wr1_ui = (const float*)d_in[20];
    const float* Wl1_iu = (const float*)d_in[21];
    const float* bl1_iu = (const float*)d_in[22];
    const float* Wr1_iu = (const float*)d_in[23];
    const float* g1_u = (const float*)d_in[24];
    const float* b1_u = (const float*)d_in[25];
    const float* g1_i = (const float*)d_in[26];
    const float* b1_i = (const float*)d_in[27];

    const int E = in_sizes[2] / 2;

    float *hu, *hi, *agg_u, *agg_i, *hu1, *hi1, *aui, *aiu, *a64u, *a64i, *inv_u, *inv_i;
    int *cnt_u, *cnt_i;
    cudaGetSymbolAddress((void**)&hu, g_hu);
    cudaGetSymbolAddress((void**)&hi, g_hi);
    cudaGetSymbolAddress((void**)&agg_u, g_agg_u);
    cudaGetSymbolAddress((void**)&agg_i, g_agg_i);
    cudaGetSymbolAddress((void**)&hu1, g_hu1);
    cudaGetSymbolAddress((void**)&hi1, g_hi1);
    cudaGetSymbolAddress((void**)&aui, g_aui);
    cudaGetSymbolAddress((void**)&aiu, g_aiu);
    cudaGetSymbolAddress((void**)&a64u, g_agg64_u);
    cudaGetSymbolAddress((void**)&a64i, g_agg64_i);
    cudaGetSymbolAddress((void**)&cnt_u, g_cnt_u);
    cudaGetSymbolAddress((void**)&cnt_i, g_cnt_i);
    cudaGetSymbolAddress((void**)&inv_u, g_inv_u);
    cudaGetSymbolAddress((void**)&inv_i, g_inv_i);

    __nv_bfloat16 *wpu_h, *wpu_l, *wpi_h, *wpi_l;
    __nv_bfloat16 *wl0ui_h, *wl0ui_l, *wr0ui_h, *wr0ui_l, *wl0iu_h, *wl0iu_l, *wr0iu_h, *wr0iu_l;
    __nv_bfloat16 *wl1ui_h, *wl1ui_l, *wr1ui_h, *wr1ui_l, *wl1iu_h, *wl1iu_l, *wr1iu_h, *wr1iu_l;
    cudaGetSymbolAddress((void**)&wpu_h, g_wpu_h);   cudaGetSymbolAddress((void**)&wpu_l, g_wpu_l);
    cudaGetSymbolAddress((void**)&wpi_h, g_wpi_h);   cudaGetSymbolAddress((void**)&wpi_l, g_wpi_l);
    cudaGetSymbolAddress((void**)&wl0ui_h, g_wl0ui_h); cudaGetSymbolAddress((void**)&wl0ui_l, g_wl0ui_l);
    cudaGetSymbolAddress((void**)&wr0ui_h, g_wr0ui_h); cudaGetSymbolAddress((void**)&wr0ui_l, g_wr0ui_l);
    cudaGetSymbolAddress((void**)&wl0iu_h, g_wl0iu_h); cudaGetSymbolAddress((void**)&wl0iu_l, g_wl0iu_l);
    cudaGetSymbolAddress((void**)&wr0iu_h, g_wr0iu_h); cudaGetSymbolAddress((void**)&wr0iu_l, g_wr0iu_l);
    cudaGetSymbolAddress((void**)&wl1ui_h, g_wl1ui_h); cudaGetSymbolAddress((void**)&wl1ui_l, g_wl1ui_l);
    cudaGetSymbolAddress((void**)&wr1ui_h, g_wr1ui_h); cudaGetSymbolAddress((void**)&wr1ui_l, g_wr1ui_l);
    cudaGetSymbolAddress((void**)&wl1iu_h, g_wl1iu_h); cudaGetSymbolAddress((void**)&wl1iu_l, g_wl1iu_l);
    cudaGetSymbolAddress((void**)&wr1iu_h, g_wr1iu_h); cudaGetSymbolAddress((void**)&wr1iu_l, g_wr1iu_l);

    float* out_u = (float*)d_out;
    float* out_i = (float*)d_out + (size_t)NU * OD;

    const int SM128 = 32768 + 2 * 128 * 128;  // 65536
    const int SM64  = 32768 + 2 * 64 * 128;   // 49152
    cudaFuncSetAttribute(mma_gemm<128, false, false, false, true>, cudaFuncAttributeMaxDynamicSharedMemorySize, SM128);
    cudaFuncSetAttribute(mma_gemm<128, true, false, true, true>, cudaFuncAttributeMaxDynamicSharedMemorySize, SM128);
    cudaFuncSetAttribute(mma_gemm<64, false, false, false, false>, cudaFuncAttributeMaxDynamicSharedMemorySize, SM64);
    cudaFuncSetAttribute(mma_gemm<64, false, true, true, false>, cudaFuncAttributeMaxDynamicSharedMemorySize, SM64);

    // weight transpose/split
    {
        WCon10 P;
        P.s[0] = { Wp_u,   wpu_h,   wpu_l,   FU, HD, 128 };
        P.s[1] = { Wp_i,   wpi_h,   wpi_l,   FI, HD, 192 };
        P.s[2] = { Wl0_ui, wl0ui_h, wl0ui_l, HD, HD, 128 };
        P.s[3] = { Wr0_ui, wr0ui_h, wr0ui_l, HD, HD, 128 };
        P.s[4] = { Wl0_iu, wl0iu_h, wl0iu_l, HD, HD, 128 };
        P.s[5] = { Wr0_iu, wr0iu_h, wr0iu_l, HD, HD, 128 };
        P.s[6] = { Wl1_ui, wl1ui_h, wl1ui_l, HD, OD, 128 };
        P.s[7] = { Wr1_ui, wr1ui_h, wr1ui_l, HD, OD, 128 };
        P.s[8] = { Wl1_iu, wl1iu_h, wl1iu_l, HD, OD, 128 };
        P.s[9] = { Wr1_iu, wr1iu_h, wr1iu_l, HD, OD, 128 };
        dim3 g((192 * 128 + 255) / 256, 10);
        wconv_kernel<<<g, 256>>>(P);
    }

    // zero accumulators
    cudaMemsetAsync(agg_u, 0, (size_t)NU * HD * sizeof(float));
    cudaMemsetAsync(agg_i, 0, (size_t)NI * HD * sizeof(float));
    cudaMemsetAsync(a64u, 0, (size_t)NU * OD * sizeof(float));
    cudaMemsetAsync(a64i, 0, (size_t)NI * OD * sizeof(float));
    cudaMemsetAsync(cnt_u, 0, (size_t)NU * sizeof(int));
    cudaMemsetAsync(cnt_i, 0, (size_t)NI * sizeof(int));

    const int GM = (NU + 127) / 128;  // NU == NI

    // input projection + ReLU
    mma_gemm<128, false, false, false, true><<<GM, 256, SM128>>>(
        x_user, wpu_h, wpu_l, FU, 128, nullptr, nullptr, nullptr, 0, 0,
        nullptr, bp_u, nullptr, nullptr, hu, NU);
    mma_gemm<128, false, false, false, true><<<GM, 256, SM128>>>(
        x_item, wpi_h, wpi_l, FI, 192, nullptr, nullptr, nullptr, 0, 0,
        nullptr, bp_i, nullptr, nullptr, hi, NI);

    // degrees
    count_kernel<<<(E + 255) / 256, 256>>>(edge_ui + E, E, cnt_i);
    count_kernel<<<(E + 255) / 256, 256>>>(edge_iu + E, E, cnt_u);
    inv_kernel<<<(NI + 255) / 256, 256>>>(cnt_i, NI, inv_i);
    inv_kernel<<<(NU + 255) / 256, 256>>>(cnt_u, NU, inv_u);

    // layer 0 aggregation
    {
        int total = E * (HD / 4);
        scatter_add_kernel<HD><<<(total + 255) / 256, 256>>>(hu, edge_ui, E, agg_i);
        scatter_add_kernel<HD><<<(total + 255) / 256, 256>>>(hi, edge_iu, E, agg_u);
    }
    scale_rows_kernel<HD, 7><<<(NI * HD + 255) / 256, 256>>>(agg_i, inv_i, NI);
    scale_rows_kernel<HD, 7><<<(NU * HD + 255) / 256, 256>>>(agg_u, inv_u, NU);

    // layer 0 fused dual-GEMM + bias + LN + ReLU
    mma_gemm<128, true, false, true, true><<<GM, 256, SM128>>>(
        agg_i, wl0ui_h, wl0ui_l, HD, 128, hi, wr0ui_h, wr0ui_l, HD, 128,
        nullptr, bl0_ui, g0_i, b0_i, hi1, NI);
    mma_gemm<128, true, false, true, true><<<GM, 256, SM128>>>(
        agg_u, wl0iu_h, wl0iu_l, HD, 128, hu, wr0iu_h, wr0iu_l, HD, 128,
        nullptr, bl0_iu, g0_u, b0_u, hu1, NU);

    // layer 1: project sources first (mean is linear)
    mma_gemm<64, false, false, false, false><<<GM, 256, SM64>>>(
        hu1, wl1ui_h, wl1ui_l, HD, 128, nullptr, nullptr, nullptr, 0, 0,
        nullptr, nullptr, nullptr, nullptr, aui, NU);
    mma_gemm<64, false, false, false, false><<<GM, 256, SM64>>>(
        hi1, wl1iu_h, wl1iu_l, HD, 128, nullptr, nullptr, nullptr, 0, 0,
        nullptr, nullptr, nullptr, nullptr, aiu, NI);

    {
        int total = E * (OD / 4);
        scatter_add_kernel<OD><<<(total + 255) / 256, 256>>>(aui, edge_ui, E, a64i);
        scatter_add_kernel<OD><<<(total + 255) / 256, 256>>>(aiu, edge_iu, E, a64u);
    }
    scale_rows_kernel<OD, 6><<<(NI * OD + 255) / 256, 256>>>(a64i, inv_i, NI);
    scale_rows_kernel<OD, 6><<<(NU * OD + 255) / 256, 256>>>(a64u, inv_u, NU);

    // layer 1 final: root GEMM + aggregated + bias + LN (no ReLU)
    mma_gemm<64, false, true, true, false><<<GM, 256, SM64>>>(
        hu1, wr1iu_h, wr1iu_l, HD, 128, nullptr, nullptr, nullptr, 0, 0,
        a64u, bl1_iu, g1_u, b1_u, out_u, NU);
    mma_gemm<64, false, true, true, false><<<GM, 256, SM64>>>(
        hi1, wr1ui_h, wr1ui_l, HD, 128, nullptr, nullptr, nullptr, 0, 0,
        a64i, bl1_ui, g1_i, b1_i, out_i, NI);

    (void)n_in; (void)out_size;
}

// round 4
// speedup vs baseline: 3.3974x; 1.3537x over previous
#include <cuda_runtime.h>
#include <cuda_bf16.h>
#include <cstdint>

// ---------------- problem constants ----------------
#define NU 100000
#define NI 100000
#define FU 96
#define FI 160
#define HD 128
#define OD 64
#define EMAX 600000
#define NBLK 391   // ceil(100000/256)

// ---------------- scratch (device globals) ----------------
__device__ float g_hu   [NU * HD];
__device__ float g_hi   [NI * HD];
__device__ float g_agg_u[NU * HD];
__device__ float g_agg_i[NI * HD];
__device__ float g_hu1  [NU * HD];
__device__ float g_hi1  [NI * HD];
__device__ float g_aui  [NU * OD];
__device__ float g_aiu  [NI * OD];
__device__ float g_agg64_u[NU * OD];
__device__ float g_agg64_i[NI * OD];
__device__ int   g_cnt_u[NU];
__device__ int   g_cnt_i[NI];
__device__ int   g_off_u[NU];
__device__ int   g_off_i[NI];
__device__ int   g_pos_u[NU];
__device__ int   g_pos_i[NI];
__device__ int   g_csr_ui[EMAX];  // src users grouped by dst item
__device__ int   g_csr_iu[EMAX];  // src items grouped by dst user
__device__ int   g_part_u[512];
__device__ int   g_part_i[512];

// transposed/split bf16 weights: layout [N rows, Kpad cols], zero padded
__device__ __nv_bfloat16 g_wpu_h[128 * 128],  g_wpu_l[128 * 128];
__device__ __nv_bfloat16 g_wpi_h[128 * 192],  g_wpi_l[128 * 192];
__device__ __nv_bfloat16 g_wl0ui_h[128 * 128], g_wl0ui_l[128 * 128];
__device__ __nv_bfloat16 g_wr0ui_h[128 * 128], g_wr0ui_l[128 * 128];
__device__ __nv_bfloat16 g_wl0iu_h[128 * 128], g_wl0iu_l[128 * 128];
__device__ __nv_bfloat16 g_wr0iu_h[128 * 128], g_wr0iu_l[128 * 128];
__device__ __nv_bfloat16 g_wl1ui_h[64 * 128],  g_wl1ui_l[64 * 128];
__device__ __nv_bfloat16 g_wr1ui_h[64 * 128],  g_wr1ui_l[64 * 128];
__device__ __nv_bfloat16 g_wl1iu_h[64 * 128],  g_wl1iu_l[64 * 128];
__device__ __nv_bfloat16 g_wr1iu_h[64 * 128],  g_wr1iu_l[64 * 128];

// ---------------- helpers ----------------
__device__ __forceinline__ uint32_t smem_u32(const void* p) {
    uint32_t a;
    asm("{ .reg .u64 t; cvta.to.shared.u64 t, %1; cvt.u32.u64 %0, t; }" : "=r"(a) : "l"(p));
    return a;
}
#define SWZ(x) ((x) ^ (((x) >> 3) & 0x70))

__device__ __forceinline__ void ldm4(uint32_t* r, uint32_t addr) {
    asm volatile("ldmatrix.sync.aligned.m8n8.x4.shared.b16 {%0,%1,%2,%3}, [%4];"
        : "=r"(r[0]), "=r"(r[1]), "=r"(r[2]), "=r"(r[3]) : "r"(addr));
}
__device__ __forceinline__ void mma_bf16(float* c, const uint32_t* a, uint32_t b0, uint32_t b1) {
    asm volatile("mma.sync.aligned.m16n8k16.row.col.f32.bf16.bf16.f32 "
        "{%0,%1,%2,%3}, {%4,%5,%6,%7}, {%8,%9}, {%0,%1,%2,%3};"
        : "+f"(c[0]), "+f"(c[1]), "+f"(c[2]), "+f"(c[3])
        : "r"(a[0]), "r"(a[1]), "r"(a[2]), "r"(a[3]), "r"(b0), "r"(b1));
}

// ---------------- degree / CSR build ----------------
__global__ void count_kernel(const int* __restrict__ dst, int E, int* __restrict__ cnt) {
    int e = blockIdx.x * blockDim.x + threadIdx.x;
    if (e < E) atomicAdd(&cnt[dst[e]], 1);
}

__global__ void scan_part_kernel(const int* __restrict__ cnt, int n, int* __restrict__ part) {
    __shared__ int sh[256];
    int i = blockIdx.x * 256 + threadIdx.x;
    sh[threadIdx.x] = (i < n) ? cnt[i] : 0;
    __syncthreads();
    for (int s = 128; s > 0; s >>= 1) {
        if (threadIdx.x < s) sh[threadIdx.x] += sh[threadIdx.x + s];
        __syncthreads();
    }
    if (threadIdx.x == 0) part[blockIdx.x] = sh[0];
}

__global__ void scan_partials_kernel(int* __restrict__ part, int nb) {
    __shared__ int sh[512];
    int t = threadIdx.x;
    int v = (t < nb) ? part[t] : 0;
    sh[t] = v;
    __syncthreads();
    for (int o = 1; o < 512; o <<= 1) {
        int x = (t >= o) ? sh[t - o] : 0;
        __syncthreads();
        sh[t] += x;
        __syncthreads();
    }
    if (t < nb) part[t] = sh[t] - v;  // exclusive
}

__global__ void scan_final_kernel(const int* __restrict__ cnt, const int* __restrict__ part,
                                  int n, int* __restrict__ off, int* __restrict__ pos) {
    __shared__ int sh[256];
    int t = threadIdx.x;
    int i = blockIdx.x * 256 + t;
    int v = (i < n) ? cnt[i] : 0;
    sh[t] = v;
    __syncthreads();
    for (int o = 1; o < 256; o <<= 1) {
        int x = (t >= o) ? sh[t - o] : 0;
        __syncthreads();
        sh[t] += x;
        __syncthreads();
    }
    if (i < n) {
        int e = sh[t] - v + part[blockIdx.x];
        off[i] = e;
        pos[i] = e;
    }
}

__global__ void build_csr_kernel(const int* __restrict__ edge, int E,
                                 int* __restrict__ pos, int* __restrict__ csr) {
    int e = blockIdx.x * blockDim.x + threadIdx.x;
    if (e < E) {
        int s = edge[e];
        int d = edge[E + e];
        int idx = atomicAdd(&pos[d], 1);
        csr[idx] = s;
    }
}

// ---------------- gather-mean aggregation (no atomics) ----------------
// group of G = C/4 lanes per destination row; each lane owns 4 consecutive floats.
template <int C>
__global__ void gather_mean_kernel(const float* __restrict__ feat, const int* __restrict__ csr,
                                   const int* __restrict__ off, const int* __restrict__ cnt,
                                   float* __restrict__ out, int N) {
    constexpr int G = C / 4;
    int gid = (int)((blockIdx.x * (size_t)blockDim.x + threadIdx.x) / G);
    if (gid >= N) return;
    const int c4 = (threadIdx.x & (G - 1)) * 4;
    const int beg = __ldg(&off[gid]);
    const int deg = __ldg(&cnt[gid]);

    float4 a0 = make_float4(0.f, 0.f, 0.f, 0.f);
    float4 a1 = make_float4(0.f, 0.f, 0.f, 0.f);
    int e = 0;
    for (; e + 1 < deg; e += 2) {
        int s0 = __ldg(&csr[beg + e]);
        int s1 = __ldg(&csr[beg + e + 1]);
        float4 v0 = *(const float4*)(feat + (size_t)s0 * C + c4);
        float4 v1 = *(const float4*)(feat + (size_t)s1 * C + c4);
        a0.x += v0.x; a0.y += v0.y; a0.z += v0.z; a0.w += v0.w;
        a1.x += v1.x; a1.y += v1.y; a1.z += v1.z; a1.w += v1.w;
    }
    if (e < deg) {
        int s0 = __ldg(&csr[beg + e]);
        float4 v0 = *(const float4*)(feat + (size_t)s0 * C + c4);
        a0.x += v0.x; a0.y += v0.y; a0.z += v0.z; a0.w += v0.w;
    }
    const float sc = 1.0f / fmaxf((float)deg, 1.0f);
    float4 r;
    r.x = (a0.x + a1.x) * sc;
    r.y = (a0.y + a1.y) * sc;
    r.z = (a0.z + a1.z) * sc;
    r.w = (a0.w + a1.w) * sc;
    *(float4*)(out + (size_t)gid * C + c4) = r;
}

// weight transpose + bf16 hi/lo split: W [K,N] fp32 -> Wt [N,Kpad] bf16 (hi,lo), zero pad
struct WCon { const float* w; __nv_bfloat16* h; __nv_bfloat16* l; int K, N, Kpad; };
struct WCon10 { WCon s[10]; };
__global__ void wconv_kernel(WCon10 P) {
    WCon w = P.s[blockIdx.y];
    int idx = blockIdx.x * blockDim.x + threadIdx.x;
    if (idx >= w.N * w.Kpad) return;
    int n = idx / w.Kpad, k = idx % w.Kpad;
    float x = (k < w.K) ? w.w[(size_t)k * w.N + n] : 0.0f;
    __nv_bfloat16 h = __float2bfloat16(x);
    w.h[idx] = h;
    w.l[idx] = __float2bfloat16(x - __bfloat162float(h));
}

// ---------------- HMMA (mma.sync) GEMM ----------------
// out[M,BN] = post( A1[M,K1]@W1 (+ A2@W2) (+ Dext) (+ bias) ), post = opt LN then opt ReLU.
// 3-pass bf16 split (hi*hi + hi*lo + lo*hi), fp32 accum in registers.
// Block: 128 rows, 8 warps, warp = 16 rows x BN cols (LN intra-warp over quads).

template <int BN, bool FUSE2, bool HAS_D, bool DO_LN, bool DO_RELU>
__global__ __launch_bounds__(256, 2)
void mma_gemm(const float* __restrict__ A1, const __nv_bfloat16* __restrict__ W1h, const __nv_bfloat16* __restrict__ W1l,
              int K1, int K1pad,
              const float* __restrict__ A2, const __nv_bfloat16* __restrict__ W2h, const __nv_bfloat16* __restrict__ W2l,
              int K2, int K2pad,
              const float* __restrict__ Dext, const float* __restrict__ bias,
              const float* __restrict__ gamma, const float* __restrict__ beta,
              float* __restrict__ out, int M) {
    static_assert(BN == 64 || BN == 128, "");
    constexpr int FN = BN / 8;

    extern __shared__ char smem[];
    const uint32_t sb = smem_u32(smem);
    const uint32_t aHiB = sb;
    const uint32_t aLoB = sb + 16384;
    const uint32_t bHiB = sb + 32768;
    const uint32_t bLoB = bHiB + BN * 128;

    const int tid = threadIdx.x;
    const int warp = tid >> 5;
    const int lane = tid & 31;
    const int r0 = blockIdx.x * 128;

    float acc[FN][4];
#pragma unroll
    for (int i = 0; i < FN; i++)
#pragma unroll
        for (int j = 0; j < 4; j++) acc[i][j] = 0.0f;

    // staging mapping
    const int ar = tid >> 1;
    const int acb = (tid & 1) * 32;
    constexpr int TPR = 256 / BN;
    constexpr int WNC = 64 / TPR;
    const int bn = tid / TPR;
    const int bq = tid % TPR;

    // compute-phase lane constants
    const uint32_t a_row = warp * 16 + (lane & 15);
    const uint32_t a_rowoff = a_row * 128;
    const uint32_t a_xm = (a_row & 7) * 16;
    const uint32_t a_khalf = ((lane >> 4) & 1) * 16;
    const uint32_t b_rowbase = ((lane & 7) + ((lane >> 4) & 1) * 8) * 128;
    const uint32_t b_xm = (lane & 7) * 16;
    const uint32_t b_khalf = ((lane >> 3) & 1) * 16;

    const int nch1 = K1pad >> 6;
    const int nch = nch1 + (FUSE2 ? (K2pad >> 6) : 0);

    for (int c = 0; c < nch; c++) {
        if (c) __syncthreads();

        const float* A;
        const __nv_bfloat16 *Wh, *Wl;
        int k0, K, Kpad;
        if (!FUSE2 || c < nch1) { A = A1; Wh = W1h; Wl = W1l; k0 = c * 64; K = K1; Kpad = K1pad; }
        else                    { A = A2; Wh = W2h; Wl = W2l; k0 = (c - nch1) * 64; K = K2; Kpad = K2pad; }

        // ---- stage A (fp32 -> bf16 hi/lo, swizzled) ----
        {
            const int grow = r0 + ar;
            const float* arow = A + (size_t)grow * K;
#pragma unroll
            for (int i = 0; i < 4; i++) {
                const int cc = acb + i * 8;
                float x[8];
#pragma unroll
                for (int j = 0; j < 8; j++) x[j] = 0.0f;
                if (grow < M && (k0 + cc) < K) {
                    float4 v0 = *(const float4*)(arow + k0 + cc);
                    float4 v1 = *(const float4*)(arow + k0 + cc + 4);
                    x[0] = v0.x; x[1] = v0.y; x[2] = v0.z; x[3] = v0.w;
                    x[4] = v1.x; x[5] = v1.y; x[6] = v1.z; x[7] = v1.w;
                }
                uint32_t hi[4], lo[4];
#pragma unroll
                for (int j = 0; j < 4; j++) {
                    __nv_bfloat16 h0 = __float2bfloat16(x[2 * j]);
                    __nv_bfloat16 h1 = __float2bfloat16(x[2 * j + 1]);
                    float l0 = x[2 * j] - __bfloat162float(h0);
                    float l1 = x[2 * j + 1] - __bfloat162float(h1);
                    __nv_bfloat16 e0 = __float2bfloat16(l0);
                    __nv_bfloat16 e1 = __float2bfloat16(l1);
                    hi[j] = (uint32_t)__bfloat16_as_ushort(h0) | ((uint32_t)__bfloat16_as_ushort(h1) << 16);
                    lo[j] = (uint32_t)__bfloat16_as_ushort(e0) | ((uint32_t)__bfloat16_as_ushort(e1) << 16);
                }
                const uint32_t off = SWZ(ar * 128 + cc * 2);
                asm volatile("st.shared.v4.b32 [%0], {%1, %2, %3, %4};" :: "r"(aHiB + off), "r"(hi[0]), "r"(hi[1]), "r"(hi[2]), "r"(hi[3]) : "memory");
                asm volatile("st.shared.v4.b32 [%0], {%1, %2, %3, %4};" :: "r"(aLoB + off), "r"(lo[0]), "r"(lo[1]), "r"(lo[2]), "r"(lo[3]) : "memory");
            }
        }
        // ---- stage B (pre-split bf16 [BN, Kpad], swizzled copy) ----
        {
#pragma unroll
            for (int i = 0; i < WNC / 8; i++) {
                const int ck = bq * WNC + i * 8;
                const size_t so = (size_t)bn * Kpad + k0 + ck;
                uint4 vh = *(const uint4*)(Wh + so);
                uint4 vl = *(const uint4*)(Wl + so);
                const uint32_t off = SWZ(bn * 128 + ck * 2);
                asm volatile("st.shared.v4.b32 [%0], {%1, %2, %3, %4};" :: "r"(bHiB + off), "r"(vh.x), "r"(vh.y), "r"(vh.z), "r"(vh.w) : "memory");
                asm volatile("st.shared.v4.b32 [%0], {%1, %2, %3, %4};" :: "r"(bLoB + off), "r"(vl.x), "r"(vl.y), "r"(vl.z), "r"(vl.w) : "memory");
            }
        }
        __syncthreads();

        // ---- compute ----
#pragma unroll
        for (int ks = 0; ks < 4; ks++) {
            const uint32_t akb = ((uint32_t)(ks * 32) + a_khalf) ^ a_xm;
            uint32_t ah[4], al[4];
            ldm4(ah, aHiB + a_rowoff + akb);
            ldm4(al, aLoB + a_rowoff + akb);
            const uint32_t bkb = ((uint32_t)(ks * 32) + b_khalf) ^ b_xm;
#pragma unroll
            for (int j = 0; j < FN / 2; j++) {
                uint32_t bh[4], bl[4];
                const uint32_t boff = b_rowbase + (uint32_t)j * 2048;
                ldm4(bh, bHiB + boff + bkb);
                ldm4(bl, bLoB + boff + bkb);
                mma_bf16(acc[2 * j],     ah, bh[0], bh[1]);
                mma_bf16(acc[2 * j],     ah, bl[0], bl[1]);
                mma_bf16(acc[2 * j],     al, bh[0], bh[1]);
                mma_bf16(acc[2 * j + 1], ah, bh[2], bh[3]);
                mma_bf16(acc[2 * j + 1], ah, bl[2], bl[3]);
                mma_bf16(acc[2 * j + 1], al, bh[2], bh[3]);
            }
        }
    }

    // ---- epilogue ----
    const int row0 = r0 + warp * 16 + (lane >> 2);
    const int row1 = row0 + 8;
    const int cb = (lane & 3) * 2;

    if (bias) {
#pragma unroll
        for (int fn = 0; fn < FN; fn++) {
            float2 bv = __ldg((const float2*)(bias + fn * 8 + cb));
            acc[fn][0] += bv.x; acc[fn][1] += bv.y;
            acc[fn][2] += bv.x; acc[fn][3] += bv.y;
        }
    }
    if (HAS_D) {
        if (row0 < M) {
#pragma unroll
            for (int fn = 0; fn < FN; fn++) {
                float2 dv = __ldg((const float2*)(Dext + (size_t)row0 * BN + fn * 8 + cb));
                acc[fn][0] += dv.x; acc[fn][1] += dv.y;
            }
        }
        if (row1 < M) {
#pragma unroll
            for (int fn = 0; fn < FN; fn++) {
                float2 dv = __ldg((const float2*)(Dext + (size_t)row1 * BN + fn * 8 + cb));
                acc[fn][2] += dv.x; acc[fn][3] += dv.y;
            }
        }
    }
    if (DO_LN) {
        float s1a = 0.f, s2a = 0.f, s1b = 0.f, s2b = 0.f;
#pragma unroll
        for (int fn = 0; fn < FN; fn++) {
            s1a += acc[fn][0] + acc[fn][1];
            s2a += acc[fn][0] * acc[fn][0] + acc[fn][1] * acc[fn][1];
            s1b += acc[fn][2] + acc[fn][3];
            s2b += acc[fn][2] * acc[fn][2] + acc[fn][3] * acc[fn][3];
        }
#pragma unroll
        for (int o = 1; o < 4; o <<= 1) {
            s1a += __shfl_xor_sync(0xFFFFFFFFu, s1a, o);
            s2a += __shfl_xor_sync(0xFFFFFFFFu, s2a, o);
            s1b += __shfl_xor_sync(0xFFFFFFFFu, s1b, o);
            s2b += __shfl_xor_sync(0xFFFFFFFFu, s2b, o);
        }
        const float inv_n = 1.0f / BN;
        float ma = s1a * inv_n, mb = s1b * inv_n;
        float ra = rsqrtf(s2a * inv_n - ma * ma + 1e-5f);
        float rb = rsqrtf(s2b * inv_n - mb * mb + 1e-5f);
#pragma unroll
        for (int fn = 0; fn < FN; fn++) {
            float2 g = __ldg((const float2*)(gamma + fn * 8 + cb));
            float2 b = __ldg((const float2*)(beta + fn * 8 + cb));
            acc[fn][0] = (acc[fn][0] - ma) * ra * g.x + b.x;
            acc[fn][1] = (acc[fn][1] - ma) * ra * g.y + b.y;
            acc[fn][2] = (acc[fn][2] - mb) * rb * g.x + b.x;
            acc[fn][3] = (acc[fn][3] - mb) * rb * g.y + b.y;
        }
    }
    if (DO_RELU) {
#pragma unroll
        for (int fn = 0; fn < FN; fn++)
#pragma unroll
            for (int j = 0; j < 4; j++) acc[fn][j] = fmaxf(acc[fn][j], 0.0f);
    }
    if (row0 < M) {
#pragma unroll
        for (int fn = 0; fn < FN; fn++)
            *(float2*)(out + (size_t)row0 * BN + fn * 8 + cb) = make_float2(acc[fn][0], acc[fn][1]);
    }
    if (row1 < M) {
#pragma unroll
        for (int fn = 0; fn < FN; fn++)
            *(float2*)(out + (size_t)row1 * BN + fn * 8 + cb) = make_float2(acc[fn][2], acc[fn][3]);
    }
}

// ---------------- host launcher ----------------
extern "C" void kernel_launch(void* const* d_in, const int* in_sizes, int n_in,
                              void* d_out, int out_size) {
    const float* x_user = (const float*)d_in[0];
    const float* x_item = (const float*)d_in[1];
    const int* edge_ui = (const int*)d_in[2];
    const int* edge_iu = (const int*)d_in[3];
    const float* Wp_u = (const float*)d_in[4];
    const float* bp_u = (const float*)d_in[5];
    const float* Wp_i = (const float*)d_in[6];
    const float* bp_i = (const float*)d_in[7];
    const float* Wl0_ui = (const float*)d_in[8];
    const float* bl0_ui = (const float*)d_in[9];
    const float* Wr0_ui = (const float*)d_in[10];
    const float* Wl0_iu = (const float*)d_in[11];
    const float* bl0_iu = (const float*)d_in[12];
    const float* Wr0_iu = (const float*)d_in[13];
    const float* g0_u = (const float*)d_in[14];
    const float* b0_u = (const float*)d_in[15];
    const float* g0_i = (const float*)d_in[16];
    const float* b0_i = (const float*)d_in[17];
    const float* Wl1_ui = (const float*)d_in[18];
    const float* bl1_ui = (const float*)d_in[19];
    const float* Wr1_ui = (const float*)d_in[20];
    const float* Wl1_iu = (const float*)d_in[21];
    const float* bl1_iu = (const float*)d_in[22];
    const float* Wr1_iu = (const float*)d_in[23];
    const float* g1_u = (const float*)d_in[24];
    const float* b1_u = (const float*)d_in[25];
    const float* g1_i = (const float*)d_in[26];
    const float* b1_i = (const float*)d_in[27];

    const int E = in_sizes[2] / 2;

    float *hu, *hi, *agg_u, *agg_i, *hu1, *hi1, *aui, *aiu, *a64u, *a64i;
    int *cnt_u, *cnt_i, *off_u, *off_i, *pos_u, *pos_i, *csr_ui, *csr_iu, *part_u, *part_i;
    cudaGetSymbolAddress((void**)&hu, g_hu);
    cudaGetSymbolAddress((void**)&hi, g_hi);
    cudaGetSymbolAddress((void**)&agg_u, g_agg_u);
    cudaGetSymbolAddress((void**)&agg_i, g_agg_i);
    cudaGetSymbolAddress((void**)&hu1, g_hu1);
    cudaGetSymbolAddress((void**)&hi1, g_hi1);
    cudaGetSymbolAddress((void**)&aui, g_aui);
    cudaGetSymbolAddress((void**)&aiu, g_aiu);
    cudaGetSymbolAddress((void**)&a64u, g_agg64_u);
    cudaGetSymbolAddress((void**)&a64i, g_agg64_i);
    cudaGetSymbolAddress((void**)&cnt_u, g_cnt_u);
    cudaGetSymbolAddress((void**)&cnt_i, g_cnt_i);
    cudaGetSymbolAddress((void**)&off_u, g_off_u);
    cudaGetSymbolAddress((void**)&off_i, g_off_i);
    cudaGetSymbolAddress((void**)&pos_u, g_pos_u);
    cudaGetSymbolAddress((void**)&pos_i, g_pos_i);
    cudaGetSymbolAddress((void**)&csr_ui, g_csr_ui);
    cudaGetSymbolAddress((void**)&csr_iu, g_csr_iu);
    cudaGetSymbolAddress((void**)&part_u, g_part_u);
    cudaGetSymbolAddress((void**)&part_i, g_part_i);

    __nv_bfloat16 *wpu_h, *wpu_l, *wpi_h, *wpi_l;
    __nv_bfloat16 *wl0ui_h, *wl0ui_l, *wr0ui_h, *wr0ui_l, *wl0iu_h, *wl0iu_l, *wr0iu_h, *wr0iu_l;
    __nv_bfloat16 *wl1ui_h, *wl1ui_l, *wr1ui_h, *wr1ui_l, *wl1iu_h, *wl1iu_l, *wr1iu_h, *wr1iu_l;
    cudaGetSymbolAddress((void**)&wpu_h, g_wpu_h);   cudaGetSymbolAddress((void**)&wpu_l, g_wpu_l);
    cudaGetSymbolAddress((void**)&wpi_h, g_wpi_h);   cudaGetSymbolAddress((void**)&wpi_l, g_wpi_l);
    cudaGetSymbolAddress((void**)&wl0ui_h, g_wl0ui_h); cudaGetSymbolAddress((void**)&wl0ui_l, g_wl0ui_l);
    cudaGetSymbolAddress((void**)&wr0ui_h, g_wr0ui_h); cudaGetSymbolAddress((void**)&wr0ui_l, g_wr0ui_l);
    cudaGetSymbolAddress((void**)&wl0iu_h, g_wl0iu_h); cudaGetSymbolAddress((void**)&wl0iu_l, g_wl0iu_l);
    cudaGetSymbolAddress((void**)&wr0iu_h, g_wr0iu_h); cudaGetSymbolAddress((void**)&wr0iu_l, g_wr0iu_l);
    cudaGetSymbolAddress((void**)&wl1ui_h, g_wl1ui_h); cudaGetSymbolAddress((void**)&wl1ui_l, g_wl1ui_l);
    cudaGetSymbolAddress((void**)&wr1ui_h, g_wr1ui_h); cudaGetSymbolAddress((void**)&wr1ui_l, g_wr1ui_l);
    cudaGetSymbolAddress((void**)&wl1iu_h, g_wl1iu_h); cudaGetSymbolAddress((void**)&wl1iu_l, g_wl1iu_l);
    cudaGetSymbolAddress((void**)&wr1iu_h, g_wr1iu_h); cudaGetSymbolAddress((void**)&wr1iu_l, g_wr1iu_l);

    float* out_u = (float*)d_out;
    float* out_i = (float*)d_out + (size_t)NU * OD;

    const int SM128 = 32768 + 2 * 128 * 128;  // 65536
    const int SM64  = 32768 + 2 * 64 * 128;   // 49152
    cudaFuncSetAttribute(mma_gemm<128, false, false, false, true>, cudaFuncAttributeMaxDynamicSharedMemorySize, SM128);
    cudaFuncSetAttribute(mma_gemm<128, true, false, true, true>, cudaFuncAttributeMaxDynamicSharedMemorySize, SM128);
    cudaFuncSetAttribute(mma_gemm<64, false, false, false, false>, cudaFuncAttributeMaxDynamicSharedMemorySize, SM64);
    cudaFuncSetAttribute(mma_gemm<64, false, true, true, false>, cudaFuncAttributeMaxDynamicSharedMemorySize, SM64);

    // weight transpose/split
    {
        WCon10 P;
        P.s[0] = { Wp_u,   wpu_h,   wpu_l,   FU, HD, 128 };
        P.s[1] = { Wp_i,   wpi_h,   wpi_l,   FI, HD, 192 };
        P.s[2] = { Wl0_ui, wl0ui_h, wl0ui_l, HD, HD, 128 };
        P.s[3] = { Wr0_ui, wr0ui_h, wr0ui_l, HD, HD, 128 };
        P.s[4] = { Wl0_iu, wl0iu_h, wl0iu_l, HD, HD, 128 };
        P.s[5] = { Wr0_iu, wr0iu_h, wr0iu_l, HD, HD, 128 };
        P.s[6] = { Wl1_ui, wl1ui_h, wl1ui_l, HD, OD, 128 };
        P.s[7] = { Wr1_ui, wr1ui_h, wr1ui_l, HD, OD, 128 };
        P.s[8] = { Wl1_iu, wl1iu_h, wl1iu_l, HD, OD, 128 };
        P.s[9] = { Wr1_iu, wr1iu_h, wr1iu_l, HD, OD, 128 };
        dim3 g((192 * 128 + 255) / 256, 10);
        wconv_kernel<<<g, 256>>>(P);
    }

    // degrees + CSR (built once, reused by both layers)
    cudaMemsetAsync(cnt_u, 0, (size_t)NU * sizeof(int));
    cudaMemsetAsync(cnt_i, 0, (size_t)NI * sizeof(int));
    count_kernel<<<(E + 255) / 256, 256>>>(edge_ui + E, E, cnt_i);
    count_kernel<<<(E + 255) / 256, 256>>>(edge_iu + E, E, cnt_u);
    scan_part_kernel<<<NBLK, 256>>>(cnt_i, NI, part_i);
    scan_part_kernel<<<NBLK, 256>>>(cnt_u, NU, part_u);
    scan_partials_kernel<<<1, 512>>>(part_i, NBLK);
    scan_partials_kernel<<<1, 512>>>(part_u, NBLK);
    scan_final_kernel<<<NBLK, 256>>>(cnt_i, part_i, NI, off_i, pos_i);
    scan_final_kernel<<<NBLK, 256>>>(cnt_u, part_u, NU, off_u, pos_u);
    build_csr_kernel<<<(E + 255) / 256, 256>>>(edge_ui, E, pos_i, csr_ui);
    build_csr_kernel<<<(E + 255) / 256, 256>>>(edge_iu, E, pos_u, csr_iu);

    const int GM = (NU + 127) / 128;  // NU == NI

    // input projection + ReLU
    mma_gemm<128, false, false, false, true><<<GM, 256, SM128>>>(
        x_user, wpu_h, wpu_l, FU, 128, nullptr, nullptr, nullptr, 0, 0,
        nullptr, bp_u, nullptr, nullptr, hu, NU);
    mma_gemm<128, false, false, false, true><<<GM, 256, SM128>>>(
        x_item, wpi_h, wpi_l, FI, 192, nullptr, nullptr, nullptr, 0, 0,
        nullptr, bp_i, nullptr, nullptr, hi, NI);

    // layer 0 aggregation: pure gather, mean fused
    {
        const int thr = 256;
        const long tot128 = (long)NI * (HD / 4);
        gather_mean_kernel<HD><<<(int)((tot128 + thr - 1) / thr), thr>>>(hu, csr_ui, off_i, cnt_i, agg_i, NI);
        gather_mean_kernel<HD><<<(int)((tot128 + thr - 1) / thr), thr>>>(hi, csr_iu, off_u, cnt_u, agg_u, NU);
    }

    // layer 0 fused dual-GEMM + bias + LN + ReLU
    mma_gemm<128, true, false, true, true><<<GM, 256, SM128>>>(
        agg_i, wl0ui_h, wl0ui_l, HD, 128, hi, wr0ui_h, wr0ui_l, HD, 128,
        nullptr, bl0_ui, g0_i, b0_i, hi1, NI);
    mma_gemm<128, true, false, true, true><<<GM, 256, SM128>>>(
        agg_u, wl0iu_h, wl0iu_l, HD, 128, hu, wr0iu_h, wr0iu_l, HD, 128,
        nullptr, bl0_iu, g0_u, b0_u, hu1, NU);

    // layer 1: project sources first (mean is linear)
    mma_gemm<64, false, false, false, false><<<GM, 256, SM64>>>(
        hu1, wl1ui_h, wl1ui_l, HD, 128, nullptr, nullptr, nullptr, 0, 0,
        nullptr, nullptr, nullptr, nullptr, aui, NU);
    mma_gemm<64, false, false, false, false><<<GM, 256, SM64>>>(
        hi1, wl1iu_h, wl1iu_l, HD, 128, nullptr, nullptr, nullptr, 0, 0,
        nullptr, nullptr, nullptr, nullptr, aiu, NI);

    // layer 1 aggregation (C=64), same CSR
    {
        const int thr = 256;
        const long tot64 = (long)NI * (OD / 4);
        gather_mean_kernel<OD><<<(int)((tot64 + thr - 1) / thr), thr>>>(aui, csr_ui, off_i, cnt_i, a64i, NI);
        gather_mean_kernel<OD><<<(int)((tot64 + thr - 1) / thr), thr>>>(aiu, csr_iu, off_u, cnt_u, a64u, NU);
    }

    // layer 1 final: root GEMM + aggregated + bias + LN (no ReLU)
    mma_gemm<64, false, true, true, false><<<GM, 256, SM64>>>(
        hu1, wr1iu_h, wr1iu_l, HD, 128, nullptr, nullptr, nullptr, 0, 0,
        a64u, bl1_iu, g1_u, b1_u, out_u, NU);
    mma_gemm<64, false, true, true, false><<<GM, 256, SM64>>>(
        hi1, wr1ui_h, wr1ui_l, HD, 128, nullptr, nullptr, nullptr, 0, 0,
        a64i, bl1_ui, g1_i, b1_i, out_i, NI);

    (void)n_in; (void)out_size;
}

// round 5
// speedup vs baseline: 3.4609x; 1.0187x over previous
#include <cuda_runtime.h>
#include <cuda_bf16.h>
#include <cstdint>

// ---------------- problem constants ----------------
#define NU 100000
#define NI 100000
#define NN 100000   // NU == NI
#define FU 96
#define FI 160
#define HD 128
#define OD 64
#define EMAX 600000
#define NBLK 391   // ceil(100000/256)

// ---------------- scratch (device globals) ----------------
__device__ float g_hu   [NN * HD];
__device__ float g_hi   [NN * HD];
__device__ float g_agg_u[NN * HD];   // also reused as tmp_u (layer-1 [proj|root])
__device__ float g_agg_i[NN * HD];   // also reused as tmp_i
__device__ float g_hu1  [NN * HD];
__device__ float g_hi1  [NN * HD];
__device__ float g_a64u [NN * OD];
__device__ float g_a64i [NN * OD];
__device__ int   g_cnt [2 * NN];   // [0..NN)=user, [NN..2NN)=item
__device__ int   g_off [2 * NN];
__device__ int   g_pos [2 * NN];
__device__ int   g_csr_iu[EMAX];   // src items grouped by dst user
__device__ int   g_csr_ui[EMAX];   // src users grouped by dst item
__device__ int   g_part[2 * 512];

// transposed/split bf16 weights: layout [N rows, Kpad cols], zero padded
__device__ __nv_bfloat16 g_wpu_h[128 * 128],  g_wpu_l[128 * 128];
__device__ __nv_bfloat16 g_wpi_h[128 * 192],  g_wpi_l[128 * 192];
__device__ __nv_bfloat16 g_wl0ui_h[128 * 128], g_wl0ui_l[128 * 128];
__device__ __nv_bfloat16 g_wr0ui_h[128 * 128], g_wr0ui_l[128 * 128];
__device__ __nv_bfloat16 g_wl0iu_h[128 * 128], g_wl0iu_l[128 * 128];
__device__ __nv_bfloat16 g_wr0iu_h[128 * 128], g_wr0iu_l[128 * 128];
__device__ __nv_bfloat16 g_w1u_h[128 * 128],  g_w1u_l[128 * 128];   // [Wl1_ui | Wr1_iu]
__device__ __nv_bfloat16 g_w1i_h[128 * 128],  g_w1i_l[128 * 128];   // [Wl1_iu | Wr1_ui]

// ---------------- helpers ----------------
__device__ __forceinline__ uint32_t smem_u32(const void* p) {
    uint32_t a;
    asm("{ .reg .u64 t; cvta.to.shared.u64 t, %1; cvt.u32.u64 %0, t; }" : "=r"(a) : "l"(p));
    return a;
}
#define SWZ(x) ((x) ^ (((x) >> 3) & 0x70))

__device__ __forceinline__ void ldm4(uint32_t* r, uint32_t addr) {
    asm volatile("ldmatrix.sync.aligned.m8n8.x4.shared.b16 {%0,%1,%2,%3}, [%4];"
        : "=r"(r[0]), "=r"(r[1]), "=r"(r[2]), "=r"(r[3]) : "r"(addr));
}
__device__ __forceinline__ void mma_bf16(float* c, const uint32_t* a, uint32_t b0, uint32_t b1) {
    asm volatile("mma.sync.aligned.m16n8k16.row.col.f32.bf16.bf16.f32 "
        "{%0,%1,%2,%3}, {%4,%5,%6,%7}, {%8,%9}, {%0,%1,%2,%3};"
        : "+f"(c[0]), "+f"(c[1]), "+f"(c[2]), "+f"(c[3])
        : "r"(a[0]), "r"(a[1]), "r"(a[2]), "r"(a[3]), "r"(b0), "r"(b1));
}

// ---------------- degree / CSR build (gridDim.y = 2 selects side) ----------------
__global__ void count_kernel(const int* __restrict__ dst0, const int* __restrict__ dst1,
                             int E, int* __restrict__ cnt) {
    int t = blockIdx.y;
    const int* dst = t ? dst1 : dst0;
    int* c = cnt + t * NN;
    int e = blockIdx.x * blockDim.x + threadIdx.x;
    if (e < E) atomicAdd(&c[dst[e]], 1);
}

__global__ void scan_part_kernel(const int* __restrict__ cnt, int* __restrict__ part) {
    __shared__ int sh[256];
    const int* c = cnt + blockIdx.y * NN;
    int* p = part + blockIdx.y * 512;
    int i = blockIdx.x * 256 + threadIdx.x;
    sh[threadIdx.x] = (i < NN) ? c[i] : 0;
    __syncthreads();
    for (int s = 128; s > 0; s >>= 1) {
        if (threadIdx.x < s) sh[threadIdx.x] += sh[threadIdx.x + s];
        __syncthreads();
    }
    if (threadIdx.x == 0) p[blockIdx.x] = sh[0];
}

__global__ void scan_partials_kernel(int* __restrict__ part, int nb) {
    __shared__ int sh[512];
    int* p = part + blockIdx.y * 512;
    int t = threadIdx.x;
    int v = (t < nb) ? p[t] : 0;
    sh[t] = v;
    __syncthreads();
    for (int o = 1; o < 512; o <<= 1) {
        int x = (t >= o) ? sh[t - o] : 0;
        __syncthreads();
        sh[t] += x;
        __syncthreads();
    }
    if (t < nb) p[t] = sh[t] - v;  // exclusive
}

__global__ void scan_final_kernel(const int* __restrict__ cnt, const int* __restrict__ part,
                                  int* __restrict__ off, int* __restrict__ pos) {
    __shared__ int sh[256];
    const int* c = cnt + blockIdx.y * NN;
    const int* p = part + blockIdx.y * 512;
    int* of = off + blockIdx.y * NN;
    int* ps = pos + blockIdx.y * NN;
    int t = threadIdx.x;
    int i = blockIdx.x * 256 + t;
    int v = (i < NN) ? c[i] : 0;
    sh[t] = v;
    __syncthreads();
    for (int o = 1; o < 256; o <<= 1) {
        int x = (t >= o) ? sh[t - o] : 0;
        __syncthreads();
        sh[t] += x;
        __syncthreads();
    }
    if (i < NN) {
        int e = sh[t] - v + p[blockIdx.x];
        of[i] = e;
        ps[i] = e;
    }
}

__global__ void build_csr_kernel(const int* __restrict__ e0, const int* __restrict__ e1,
                                 int E, int* __restrict__ pos,
                                 int* __restrict__ c0, int* __restrict__ c1) {
    int t = blockIdx.y;
    const int* edge = t ? e1 : e0;
    int* ps = pos + t * NN;
    int* csr = t ? c1 : c0;
    int e = blockIdx.x * blockDim.x + threadIdx.x;
    if (e < E) {
        int s = edge[e];
        int d = edge[E + e];
        int idx = atomicAdd(&ps[d], 1);
        csr[idx] = s;
    }
}

// ---------------- gather-mean aggregation (no atomics), dual via gridDim.y ----------------
template <int C>
__global__ void gather_mean_kernel(const float* __restrict__ fA, const int* __restrict__ csrA, float* __restrict__ oA,
                                   const float* __restrict__ fB, const int* __restrict__ csrB, float* __restrict__ oB,
                                   const int* __restrict__ off, const int* __restrict__ cnt, int S) {
    constexpr int G = C / 4;
    const int t = blockIdx.y;
    const float* feat = t ? fB : fA;
    const int* csr = t ? csrB : csrA;
    float* out = t ? oB : oA;
    const int* of = off + t * NN;
    const int* cn = cnt + t * NN;

    int gid = (int)((blockIdx.x * (size_t)blockDim.x + threadIdx.x) / G);
    if (gid >= NN) return;
    const int c4 = (threadIdx.x & (G - 1)) * 4;
    const int beg = __ldg(&of[gid]);
    const int deg = __ldg(&cn[gid]);

    float4 a0 = make_float4(0.f, 0.f, 0.f, 0.f);
    float4 a1 = make_float4(0.f, 0.f, 0.f, 0.f);
    int e = 0;
    for (; e + 1 < deg; e += 2) {
        int s0 = __ldg(&csr[beg + e]);
        int s1 = __ldg(&csr[beg + e + 1]);
        float4 v0 = *(const float4*)(feat + (size_t)s0 * S + c4);
        float4 v1 = *(const float4*)(feat + (size_t)s1 * S + c4);
        a0.x += v0.x; a0.y += v0.y; a0.z += v0.z; a0.w += v0.w;
        a1.x += v1.x; a1.y += v1.y; a1.z += v1.z; a1.w += v1.w;
    }
    if (e < deg) {
        int s0 = __ldg(&csr[beg + e]);
        float4 v0 = *(const float4*)(feat + (size_t)s0 * S + c4);
        a0.x += v0.x; a0.y += v0.y; a0.z += v0.z; a0.w += v0.w;
    }
    const float sc = 1.0f / fmaxf((float)deg, 1.0f);
    float4 r;
    r.x = (a0.x + a1.x) * sc;
    r.y = (a0.y + a1.y) * sc;
    r.z = (a0.z + a1.z) * sc;
    r.w = (a0.w + a1.w) * sc;
    *(float4*)(out + (size_t)gid * C + c4) = r;
}

// ---------------- final LN over OD=64: out = LN(root + agg + bias) ----------------
struct FinSide { const float* root; const float* agg; const float* bias; const float* g; const float* b; float* out; };
__global__ void final_ln_kernel(FinSide s0, FinSide s1) {
    FinSide s = blockIdx.y ? s1 : s0;
    const int warp = threadIdx.x >> 5;
    const int lane = threadIdx.x & 31;
    const int row = blockIdx.x * 8 + warp;
    if (row >= NN) return;
    const int c = lane * 2;
    float2 rv = *(const float2*)(s.root + (size_t)row * 128 + c);
    float2 av = *(const float2*)(s.agg + (size_t)row * 64 + c);
    float2 bv = __ldg((const float2*)(s.bias + c));
    float v0 = rv.x + av.x + bv.x;
    float v1 = rv.y + av.y + bv.y;
    float s1v = v0 + v1;
    float s2v = v0 * v0 + v1 * v1;
#pragma unroll
    for (int o = 16; o > 0; o >>= 1) {
        s1v += __shfl_xor_sync(0xFFFFFFFFu, s1v, o);
        s2v += __shfl_xor_sync(0xFFFFFFFFu, s2v, o);
    }
    float mean = s1v * (1.0f / 64.0f);
    float var = s2v * (1.0f / 64.0f) - mean * mean;
    float rstd = rsqrtf(var + 1e-5f);
    float2 gv = __ldg((const float2*)(s.g + c));
    float2 bb = __ldg((const float2*)(s.b + c));
    float2 o2;
    o2.x = (v0 - mean) * rstd * gv.x + bb.x;
    o2.y = (v1 - mean) * rstd * gv.y + bb.y;
    *(float2*)(s.out + (size_t)row * 64 + c) = o2;
}

// weight transpose + bf16 hi/lo split: W [K,N] fp32 -> Wt [N,Kpad] bf16 (hi,lo), zero pad
struct WCon { const float* w; __nv_bfloat16* h; __nv_bfloat16* l; int K, N, Kpad; };
struct WCon10 { WCon s[10]; };
__global__ void wconv_kernel(WCon10 P) {
    WCon w = P.s[blockIdx.y];
    int idx = blockIdx.x * blockDim.x + threadIdx.x;
    if (idx >= w.N * w.Kpad) return;
    int n = idx / w.Kpad, k = idx % w.Kpad;
    float x = (k < w.K) ? w.w[(size_t)k * w.N + n] : 0.0f;
    __nv_bfloat16 h = __float2bfloat16(x);
    w.h[idx] = h;
    w.l[idx] = __float2bfloat16(x - __bfloat162float(h));
}

// ---------------- HMMA (mma.sync) GEMM, BN=128, 4x2 warp tiling ----------------
// out[M,128] = post( A1[M,K1]@W1 (+ A2@W2) (+ bias) ), post = opt LN then opt ReLU.
// 3-pass bf16 split (hi*hi + hi*lo + lo*hi), fp32 accum.
// Warp (wm 0..3, wn 0..1) = 32 rows x 64 cols; B fragments reused across 2 m16 tiles.

#define BN 128

template <bool FUSE2, bool DO_LN, bool DO_RELU>
__global__ __launch_bounds__(256, 2)
void mma_gemm(const float* __restrict__ A1, const __nv_bfloat16* __restrict__ W1h, const __nv_bfloat16* __restrict__ W1l,
              int K1, int K1pad,
              const float* __restrict__ A2, const __nv_bfloat16* __restrict__ W2h, const __nv_bfloat16* __restrict__ W2l,
              int K2, int K2pad,
              const float* __restrict__ bias,
              const float* __restrict__ gamma, const float* __restrict__ beta,
              float* __restrict__ out, int M) {
    extern __shared__ char smem[];
    const uint32_t sb = smem_u32(smem);
    const uint32_t aHiB = sb;
    const uint32_t aLoB = sb + 16384;
    const uint32_t bHiB = sb + 32768;
    const uint32_t bLoB = sb + 49152;

    const int tid = threadIdx.x;
    const int warp = tid >> 5;
    const int lane = tid & 31;
    const int wm = warp & 3;
    const int wn = warp >> 2;
    const int r0 = blockIdx.x * 128;

    float acc[2][8][4];
#pragma unroll
    for (int mt = 0; mt < 2; mt++)
#pragma unroll
        for (int nt = 0; nt < 8; nt++)
#pragma unroll
            for (int j = 0; j < 4; j++) acc[mt][nt][j] = 0.0f;

    // staging mapping
    const int ar = tid >> 1;
    const int acb = (tid & 1) * 32;
    const int bn = tid >> 1;          // B row (N index)
    const int bq = tid & 1;           // half of 64 K-cols

    // compute-phase lane constants
    const uint32_t a_off0 = (uint32_t)(wm * 32 + (lane & 15)) * 128;
    const uint32_t a_off1 = a_off0 + 16 * 128;
    const uint32_t a_xm = (lane & 7) * 16;
    const uint32_t a_khalf = ((lane >> 4) & 1) * 16;
    const uint32_t b_rowbase = (uint32_t)(wn * 64 + (lane & 7) + ((lane >> 4) & 1) * 8) * 128;
    const uint32_t b_xm = (lane & 7) * 16;
    const uint32_t b_khalf = ((lane >> 3) & 1) * 16;

    const int nch1 = K1pad >> 6;
    const int nch = nch1 + (FUSE2 ? (K2pad >> 6) : 0);

    for (int c = 0; c < nch; c++) {
        if (c) __syncthreads();

        const float* A;
        const __nv_bfloat16 *Wh, *Wl;
        int k0, K, Kpad;
        if (!FUSE2 || c < nch1) { A = A1; Wh = W1h; Wl = W1l; k0 = c * 64; K = K1; Kpad = K1pad; }
        else                    { A = A2; Wh = W2h; Wl = W2l; k0 = (c - nch1) * 64; K = K2; Kpad = K2pad; }

        // ---- stage A (fp32 -> bf16 hi/lo, swizzled) ----
        {
            const int grow = r0 + ar;
            const float* arow = A + (size_t)grow * K;
#pragma unroll
            for (int i = 0; i < 4; i++) {
                const int cc = acb + i * 8;
                float x[8];
#pragma unroll
                for (int j = 0; j < 8; j++) x[j] = 0.0f;
                if (grow < M && (k0 + cc) < K) {
                    float4 v0 = *(const float4*)(arow + k0 + cc);
                    float4 v1 = *(const float4*)(arow + k0 + cc + 4);
                    x[0] = v0.x; x[1] = v0.y; x[2] = v0.z; x[3] = v0.w;
                    x[4] = v1.x; x[5] = v1.y; x[6] = v1.z; x[7] = v1.w;
                }
                uint32_t hi[4], lo[4];
#pragma unroll
                for (int j = 0; j < 4; j++) {
                    __nv_bfloat16 h0 = __float2bfloat16(x[2 * j]);
                    __nv_bfloat16 h1 = __float2bfloat16(x[2 * j + 1]);
                    float l0 = x[2 * j] - __bfloat162float(h0);
                    float l1 = x[2 * j + 1] - __bfloat162float(h1);
                    __nv_bfloat16 e0 = __float2bfloat16(l0);
                    __nv_bfloat16 e1 = __float2bfloat16(l1);
                    hi[j] = (uint32_t)__bfloat16_as_ushort(h0) | ((uint32_t)__bfloat16_as_ushort(h1) << 16);
                    lo[j] = (uint32_t)__bfloat16_as_ushort(e0) | ((uint32_t)__bfloat16_as_ushort(e1) << 16);
                }
                const uint32_t off = SWZ(ar * 128 + cc * 2);
                asm volatile("st.shared.v4.b32 [%0], {%1, %2, %3, %4};" :: "r"(aHiB + off), "r"(hi[0]), "r"(hi[1]), "r"(hi[2]), "r"(hi[3]) : "memory");
                asm volatile("st.shared.v4.b32 [%0], {%1, %2, %3, %4};" :: "r"(aLoB + off), "r"(lo[0]), "r"(lo[1]), "r"(lo[2]), "r"(lo[3]) : "memory");
            }
        }
        // ---- stage B (pre-split bf16 [128, Kpad], swizzled copy) ----
        {
#pragma unroll
            for (int i = 0; i < 4; i++) {
                const int ck = bq * 32 + i * 8;
                const size_t so = (size_t)bn * Kpad + k0 + ck;
                uint4 vh = *(const uint4*)(Wh + so);
                uint4 vl = *(const uint4*)(Wl + so);
                const uint32_t off = SWZ(bn * 128 + ck * 2);
                asm volatile("st.shared.v4.b32 [%0], {%1, %2, %3, %4};" :: "r"(bHiB + off), "r"(vh.x), "r"(vh.y), "r"(vh.z), "r"(vh.w) : "memory");
                asm volatile("st.shared.v4.b32 [%0], {%1, %2, %3, %4};" :: "r"(bLoB + off), "r"(vl.x), "r"(vl.y), "r"(vl.z), "r"(vl.w) : "memory");
            }
        }
        __syncthreads();

        // ---- compute ----
#pragma unroll
        for (int ks = 0; ks < 4; ks++) {
            const uint32_t akb = ((uint32_t)(ks * 32) + a_khalf) ^ a_xm;
            uint32_t ah[2][4], al[2][4];
            ldm4(ah[0], aHiB + a_off0 + akb);
            ldm4(ah[1], aHiB + a_off1 + akb);
            ldm4(al[0], aLoB + a_off0 + akb);
            ldm4(al[1], aLoB + a_off1 + akb);
            const uint32_t bkb = ((uint32_t)(ks * 32) + b_khalf) ^ b_xm;
#pragma unroll
            for (int j = 0; j < 4; j++) {
                uint32_t bh[4], bl[4];
                const uint32_t boff = b_rowbase + (uint32_t)j * 2048;
                ldm4(bh, bHiB + boff + bkb);
                ldm4(bl, bLoB + boff + bkb);
#pragma unroll
                for (int mt = 0; mt < 2; mt++) {
                    mma_bf16(acc[mt][2 * j],     ah[mt], bh[0], bh[1]);
                    mma_bf16(acc[mt][2 * j],     ah[mt], bl[0], bl[1]);
                    mma_bf16(acc[mt][2 * j],     al[mt], bh[0], bh[1]);
                    mma_bf16(acc[mt][2 * j + 1], ah[mt], bh[2], bh[3]);
                    mma_bf16(acc[mt][2 * j + 1], ah[mt], bl[2], bl[3]);
                    mma_bf16(acc[mt][2 * j + 1], al[mt], bh[2], bh[3]);
                }
            }
        }
    }

    // ---- epilogue ----
    const int rq = lane >> 2;
    const int cq = (lane & 3) * 2;

    if (bias) {
#pragma unroll
        for (int nt = 0; nt < 8; nt++) {
            float2 bv = __ldg((const float2*)(bias + wn * 64 + nt * 8 + cq));
#pragma unroll
            for (int mt = 0; mt < 2; mt++) {
                acc[mt][nt][0] += bv.x; acc[mt][nt][1] += bv.y;
                acc[mt][nt][2] += bv.x; acc[mt][nt][3] += bv.y;
            }
        }
    }
    if (DO_LN) {
        // partial sums per (mt, h) over this warp's 64 cols
        float s1[2][2], s2[2][2];
#pragma unroll
        for (int mt = 0; mt < 2; mt++)
#pragma unroll
            for (int h = 0; h < 2; h++) { s1[mt][h] = 0.f; s2[mt][h] = 0.f; }
#pragma unroll
        for (int mt = 0; mt < 2; mt++)
#pragma unroll
            for (int nt = 0; nt < 8; nt++) {
                s1[mt][0] += acc[mt][nt][0] + acc[mt][nt][1];
                s2[mt][0] += acc[mt][nt][0] * acc[mt][nt][0] + acc[mt][nt][1] * acc[mt][nt][1];
                s1[mt][1] += acc[mt][nt][2] + acc[mt][nt][3];
                s2[mt][1] += acc[mt][nt][2] * acc[mt][nt][2] + acc[mt][nt][3] * acc[mt][nt][3];
            }
#pragma unroll
        for (int o = 1; o < 4; o <<= 1) {
#pragma unroll
            for (int mt = 0; mt < 2; mt++)
#pragma unroll
                for (int h = 0; h < 2; h++) {
                    s1[mt][h] += __shfl_xor_sync(0xFFFFFFFFu, s1[mt][h], o);
                    s2[mt][h] += __shfl_xor_sync(0xFFFFFFFFu, s2[mt][h], o);
                }
        }
        // cross-warp (wn) combine via smem scratch: [s1|s2][wn][row]
        float* sc = (float*)smem;
        __syncthreads();  // tiles no longer needed
        if ((lane & 3) == 0) {
#pragma unroll
            for (int mt = 0; mt < 2; mt++)
#pragma unroll
                for (int h = 0; h < 2; h++) {
                    int rl = wm * 32 + mt * 16 + h * 8 + rq;
                    sc[wn * 128 + rl] = s1[mt][h];
                    sc[256 + wn * 128 + rl] = s2[mt][h];
                }
        }
        __syncthreads();
#pragma unroll
        for (int mt = 0; mt < 2; mt++)
#pragma unroll
            for (int h = 0; h < 2; h++) {
                int rl = wm * 32 + mt * 16 + h * 8 + rq;
                float S1 = sc[rl] + sc[128 + rl];
                float S2 = sc[256 + rl] + sc[384 + rl];
                float mean = S1 * (1.0f / 128.0f);
                float var = S2 * (1.0f / 128.0f) - mean * mean;
                float rstd = rsqrtf(var + 1e-5f);
                s1[mt][h] = mean;
                s2[mt][h] = rstd;
            }
#pragma unroll
        for (int nt = 0; nt < 8; nt++) {
            float2 g = __ldg((const float2*)(gamma + wn * 64 + nt * 8 + cq));
            float2 b = __ldg((const float2*)(beta + wn * 64 + nt * 8 + cq));
#pragma unroll
            for (int mt = 0; mt < 2; mt++) {
                acc[mt][nt][0] = (acc[mt][nt][0] - s1[mt][0]) * s2[mt][0] * g.x + b.x;
                acc[mt][nt][1] = (acc[mt][nt][1] - s1[mt][0]) * s2[mt][0] * g.y + b.y;
                acc[mt][nt][2] = (acc[mt][nt][2] - s1[mt][1]) * s2[mt][1] * g.x + b.x;
                acc[mt][nt][3] = (acc[mt][nt][3] - s1[mt][1]) * s2[mt][1] * g.y + b.y;
            }
        }
    }
    if (DO_RELU) {
#pragma unroll
        for (int mt = 0; mt < 2; mt++)
#pragma unroll
            for (int nt = 0; nt < 8; nt++)
#pragma unroll
                for (int j = 0; j < 4; j++) acc[mt][nt][j] = fmaxf(acc[mt][nt][j], 0.0f);
    }
#pragma unroll
    for (int mt = 0; mt < 2; mt++)
#pragma unroll
        for (int h = 0; h < 2; h++) {
            int row = r0 + wm * 32 + mt * 16 + h * 8 + rq;
            if (row < M) {
#pragma unroll
                for (int nt = 0; nt < 8; nt++)
                    *(float2*)(out + (size_t)row * BN + wn * 64 + nt * 8 + cq) =
                        make_float2(acc[mt][nt][2 * h], acc[mt][nt][2 * h + 1]);
            }
        }
}

// ---------------- host launcher ----------------
extern "C" void kernel_launch(void* const* d_in, const int* in_sizes, int n_in,
                              void* d_out, int out_size) {
    const float* x_user = (const float*)d_in[0];
    const float* x_item = (const float*)d_in[1];
    const int* edge_ui = (const int*)d_in[2];
    const int* edge_iu = (const int*)d_in[3];
    const float* Wp_u = (const float*)d_in[4];
    const float* bp_u = (const float*)d_in[5];
    const float* Wp_i = (const float*)d_in[6];
    const float* bp_i = (const float*)d_in[7];
    const float* Wl0_ui = (const float*)d_in[8];
    const float* bl0_ui = (const float*)d_in[9];
    const float* Wr0_ui = (const float*)d_in[10];
    const float* Wl0_iu = (const float*)d_in[11];
    const float* bl0_iu = (const float*)d_in[12];
    const float* Wr0_iu = (const float*)d_in[13];
    const float* g0_u = (const float*)d_in[14];
    const float* b0_u = (const float*)d_in[15];
    const float* g0_i = (const float*)d_in[16];
    const float* b0_i = (const float*)d_in[17];
    const float* Wl1_ui = (const float*)d_in[18];
    const float* bl1_ui = (const float*)d_in[19];
    const float* Wr1_ui = (const float*)d_in[20];
    const float* Wl1_iu = (const float*)d_in[21];
    const float* bl1_iu = (const float*)d_in[22];
    const float* Wr1_iu = (const float*)d_in[23];
    const float* g1_u = (const float*)d_in[24];
    const float* b1_u = (const float*)d_in[25];
    const float* g1_i = (const float*)d_in[26];
    const float* b1_i = (const float*)d_in[27];

    const int E = in_sizes[2] / 2;

    float *hu, *hi, *agg_u, *agg_i, *hu1, *hi1, *a64u, *a64i;
    int *cnt, *off, *pos, *csr_iu, *csr_ui, *part;
    cudaGetSymbolAddress((void**)&hu, g_hu);
    cudaGetSymbolAddress((void**)&hi, g_hi);
    cudaGetSymbolAddress((void**)&agg_u, g_agg_u);
    cudaGetSymbolAddress((void**)&agg_i, g_agg_i);
    cudaGetSymbolAddress((void**)&hu1, g_hu1);
    cudaGetSymbolAddress((void**)&hi1, g_hi1);
    cudaGetSymbolAddress((void**)&a64u, g_a64u);
    cudaGetSymbolAddress((void**)&a64i, g_a64i);
    cudaGetSymbolAddress((void**)&cnt, g_cnt);
    cudaGetSymbolAddress((void**)&off, g_off);
    cudaGetSymbolAddress((void**)&pos, g_pos);
    cudaGetSymbolAddress((void**)&csr_iu, g_csr_iu);
    cudaGetSymbolAddress((void**)&csr_ui, g_csr_ui);
    cudaGetSymbolAddress((void**)&part, g_part);

    __nv_bfloat16 *wpu_h, *wpu_l, *wpi_h, *wpi_l;
    __nv_bfloat16 *wl0ui_h, *wl0ui_l, *wr0ui_h, *wr0ui_l, *wl0iu_h, *wl0iu_l, *wr0iu_h, *wr0iu_l;
    __nv_bfloat16 *w1u_h, *w1u_l, *w1i_h, *w1i_l;
    cudaGetSymbolAddress((void**)&wpu_h, g_wpu_h);   cudaGetSymbolAddress((void**)&wpu_l, g_wpu_l);
    cudaGetSymbolAddress((void**)&wpi_h, g_wpi_h);   cudaGetSymbolAddress((void**)&wpi_l, g_wpi_l);
    cudaGetSymbolAddress((void**)&wl0ui_h, g_wl0ui_h); cudaGetSymbolAddress((void**)&wl0ui_l, g_wl0ui_l);
    cudaGetSymbolAddress((void**)&wr0ui_h, g_wr0ui_h); cudaGetSymbolAddress((void**)&wr0ui_l, g_wr0ui_l);
    cudaGetSymbolAddress((void**)&wl0iu_h, g_wl0iu_h); cudaGetSymbolAddress((void**)&wl0iu_l, g_wl0iu_l);
    cudaGetSymbolAddress((void**)&wr0iu_h, g_wr0iu_h); cudaGetSymbolAddress((void**)&wr0iu_l, g_wr0iu_l);
    cudaGetSymbolAddress((void**)&w1u_h, g_w1u_h);   cudaGetSymbolAddress((void**)&w1u_l, g_w1u_l);
    cudaGetSymbolAddress((void**)&w1i_h, g_w1i_h);   cudaGetSymbolAddress((void**)&w1i_l, g_w1i_l);

    float* out_u = (float*)d_out;
    float* out_i = (float*)d_out + (size_t)NN * OD;

    const int SM = 65536;
    cudaFuncSetAttribute(mma_gemm<false, false, true>, cudaFuncAttributeMaxDynamicSharedMemorySize, SM);
    cudaFuncSetAttribute(mma_gemm<true, true, true>, cudaFuncAttributeMaxDynamicSharedMemorySize, SM);
    cudaFuncSetAttribute(mma_gemm<false, false, false>, cudaFuncAttributeMaxDynamicSharedMemorySize, SM);

    // weight transpose/split
    {
        WCon10 P;
        P.s[0] = { Wp_u,   wpu_h,   wpu_l,   FU, HD, 128 };
        P.s[1] = { Wp_i,   wpi_h,   wpi_l,   FI, HD, 192 };
        P.s[2] = { Wl0_ui, wl0ui_h, wl0ui_l, HD, HD, 128 };
        P.s[3] = { Wr0_ui, wr0ui_h, wr0ui_l, HD, HD, 128 };
        P.s[4] = { Wl0_iu, wl0iu_h, wl0iu_l, HD, HD, 128 };
        P.s[5] = { Wr0_iu, wr0iu_h, wr0iu_l, HD, HD, 128 };
        P.s[6] = { Wl1_ui, w1u_h,             w1u_l,             HD, OD, 128 };
        P.s[7] = { Wr1_iu, w1u_h + 64 * 128,  w1u_l + 64 * 128,  HD, OD, 128 };
        P.s[8] = { Wl1_iu, w1i_h,             w1i_l,             HD, OD, 128 };
        P.s[9] = { Wr1_ui, w1i_h + 64 * 128,  w1i_l + 64 * 128,  HD, OD, 128 };
        dim3 g((192 * 128 + 255) / 256, 10);
        wconv_kernel<<<g, 256>>>(P);
    }

    // degrees + CSR (built once, reused by both layers). t=0: user side (edge_iu), t=1: item side (edge_ui)
    cudaMemsetAsync(cnt, 0, (size_t)2 * NN * sizeof(int));
    {
        dim3 ge((E + 255) / 256, 2);
        count_kernel<<<ge, 256>>>(edge_iu + E, edge_ui + E, E, cnt);
        scan_part_kernel<<<dim3(NBLK, 2), 256>>>(cnt, part);
        scan_partials_kernel<<<dim3(1, 2), 512>>>(part, NBLK);
        scan_final_kernel<<<dim3(NBLK, 2), 256>>>(cnt, part, off, pos);
        build_csr_kernel<<<ge, 256>>>(edge_iu, edge_ui, E, pos, csr_iu, csr_ui);
    }

    const int GM = (NN + 127) / 128;

    // input projection + ReLU
    mma_gemm<false, false, true><<<GM, 256, SM>>>(
        x_user, wpu_h, wpu_l, FU, 128, nullptr, nullptr, nullptr, 0, 0,
        bp_u, nullptr, nullptr, hu, NN);
    mma_gemm<false, false, true><<<GM, 256, SM>>>(
        x_item, wpi_h, wpi_l, FI, 192, nullptr, nullptr, nullptr, 0, 0,
        bp_i, nullptr, nullptr, hi, NN);

    // layer 0 aggregation: pure gather, mean fused. t=0: agg_u <- hi via csr_iu; t=1: agg_i <- hu via csr_ui
    {
        const long tot = (long)NN * (HD / 4);
        dim3 gg((unsigned)((tot + 255) / 256), 2);
        gather_mean_kernel<HD><<<gg, 256>>>(hi, csr_iu, agg_u, hu, csr_ui, agg_i, off, cnt, HD);
    }

    // layer 0 fused dual-GEMM + bias + LN + ReLU
    mma_gemm<true, true, true><<<GM, 256, SM>>>(
        agg_i, wl0ui_h, wl0ui_l, HD, 128, hi, wr0ui_h, wr0ui_l, HD, 128,
        bl0_ui, g0_i, b0_i, hi1, NN);
    mma_gemm<true, true, true><<<GM, 256, SM>>>(
        agg_u, wl0iu_h, wl0iu_l, HD, 128, hu, wr0iu_h, wr0iu_l, HD, 128,
        bl0_iu, g0_u, b0_u, hu1, NN);

    // layer 1 combined GEMM: tmp = h1 @ [Wl1 | Wr1]  (cols 0-63 proj, 64-127 root). Reuse agg_* as tmp.
    float* tmp_u = agg_u;
    float* tmp_i = agg_i;
    mma_gemm<false, false, false><<<GM, 256, SM>>>(
        hu1, w1u_h, w1u_l, HD, 128, nullptr, nullptr, nullptr, 0, 0,
        nullptr, nullptr, nullptr, tmp_u, NN);
    mma_gemm<false, false, false><<<GM, 256, SM>>>(
        hi1, w1i_h, w1i_l, HD, 128, nullptr, nullptr, nullptr, 0, 0,
        nullptr, nullptr, nullptr, tmp_i, NN);

    // layer 1 aggregation (C=64, stride 128). t=0: a64u <- tmp_i[:, :64] via csr_iu; t=1: a64i <- tmp_u[:, :64] via csr_ui
    {
        const long tot = (long)NN * (OD / 4);
        dim3 gg((unsigned)((tot + 255) / 256), 2);
        gather_mean_kernel<OD><<<gg, 256>>>(tmp_i, csr_iu, a64u, tmp_u, csr_ui, a64i, off, cnt, HD);
    }

    // final: out = LN(root + agg + bias)
    {
        FinSide su = { tmp_u + 64, a64u, bl1_iu, g1_u, b1_u, out_u };
        FinSide si = { tmp_i + 64, a64i, bl1_ui, g1_i, b1_i, out_i };
        dim3 gf((NN + 7) / 8, 2);
        final_ln_kernel<<<gf, 256>>>(su, si);
    }

    (void)n_in; (void)out_size; (void)in_sizes;
}

// round 6
// speedup vs baseline: 3.8345x; 1.1079x over previous
#include <cuda_runtime.h>
#include <cuda_bf16.h>
#include <cstdint>

// ---------------- problem constants ----------------
#define NU 100000
#define NI 100000
#define NN 100000   // NU == NI
#define FU 96
#define FI 160
#define HD 128
#define OD 64
#define EMAX 600000
#define NBLK 391   // ceil(100000/256)

// ---------------- scratch (device globals) ----------------
__device__ float g_hu   [NN * HD];
__device__ float g_hi   [NN * HD];
__device__ float g_agg_u[NN * HD];   // reused as tmp_u (layer-1 [proj|root])
__device__ float g_agg_i[NN * HD];   // reused as tmp_i
__device__ float g_hu1  [NN * HD];
__device__ float g_hi1  [NN * HD];
__device__ int   g_cnt [2 * NN];   // [0..NN)=user, [NN..2NN)=item
__device__ int   g_off [2 * NN];
__device__ int   g_pos [2 * NN];
__device__ int   g_csr_iu[EMAX];   // src items grouped by dst user
__device__ int   g_csr_ui[EMAX];   // src users grouped by dst item
__device__ int   g_part[2 * 512];

// transposed/split bf16 weights: layout [N rows, Kpad cols], zero padded
__device__ __nv_bfloat16 g_wpu_h[128 * 128],  g_wpu_l[128 * 128];
__device__ __nv_bfloat16 g_wpi_h[128 * 192],  g_wpi_l[128 * 192];
__device__ __nv_bfloat16 g_wl0ui_h[128 * 128], g_wl0ui_l[128 * 128];
__device__ __nv_bfloat16 g_wr0ui_h[128 * 128], g_wr0ui_l[128 * 128];
__device__ __nv_bfloat16 g_wl0iu_h[128 * 128], g_wl0iu_l[128 * 128];
__device__ __nv_bfloat16 g_wr0iu_h[128 * 128], g_wr0iu_l[128 * 128];
__device__ __nv_bfloat16 g_w1u_h[128 * 128],  g_w1u_l[128 * 128];   // [Wl1_ui | Wr1_iu]
__device__ __nv_bfloat16 g_w1i_h[128 * 128],  g_w1i_l[128 * 128];   // [Wl1_iu | Wr1_ui]

// ---------------- helpers ----------------
__device__ __forceinline__ uint32_t smem_u32(const void* p) {
    uint32_t a;
    asm("{ .reg .u64 t; cvta.to.shared.u64 t, %1; cvt.u32.u64 %0, t; }" : "=r"(a) : "l"(p));
    return a;
}
#define SWZ(x) ((x) ^ (((x) >> 3) & 0x70))

__device__ __forceinline__ void ldm4(uint32_t* r, uint32_t addr) {
    asm volatile("ldmatrix.sync.aligned.m8n8.x4.shared.b16 {%0,%1,%2,%3}, [%4];"
        : "=r"(r[0]), "=r"(r[1]), "=r"(r[2]), "=r"(r[3]) : "r"(addr));
}
__device__ __forceinline__ void mma_bf16(float* c, const uint32_t* a, uint32_t b0, uint32_t b1) {
    asm volatile("mma.sync.aligned.m16n8k16.row.col.f32.bf16.bf16.f32 "
        "{%0,%1,%2,%3}, {%4,%5,%6,%7}, {%8,%9}, {%0,%1,%2,%3};"
        : "+f"(c[0]), "+f"(c[1]), "+f"(c[2]), "+f"(c[3])
        : "r"(a[0]), "r"(a[1]), "r"(a[2]), "r"(a[3]), "r"(b0), "r"(b1));
}

// ---------------- CSR build chain ----------------
__global__ void zero_cnt_kernel(int* __restrict__ cnt) {
    int i = blockIdx.x * blockDim.x + threadIdx.x;
    if (i < 2 * NN) cnt[i] = 0;
}

__global__ void count_kernel(const int* __restrict__ dst0, const int* __restrict__ dst1,
                             int E, int* __restrict__ cnt) {
    int t = blockIdx.y;
    const int* dst = t ? dst1 : dst0;
    int* c = cnt + t * NN;
    int e = blockIdx.x * blockDim.x + threadIdx.x;
    if (e < E) atomicAdd(&c[dst[e]], 1);
}

__global__ void scan_part_kernel(const int* __restrict__ cnt, int* __restrict__ part) {
    __shared__ int sh[256];
    const int* c = cnt + blockIdx.y * NN;
    int* p = part + blockIdx.y * 512;
    int i = blockIdx.x * 256 + threadIdx.x;
    sh[threadIdx.x] = (i < NN) ? c[i] : 0;
    __syncthreads();
    for (int s = 128; s > 0; s >>= 1) {
        if (threadIdx.x < s) sh[threadIdx.x] += sh[threadIdx.x + s];
        __syncthreads();
    }
    if (threadIdx.x == 0) p[blockIdx.x] = sh[0];
}

__global__ void scan_partials_kernel(int* __restrict__ part, int nb) {
    __shared__ int sh[512];
    int* p = part + blockIdx.y * 512;
    int t = threadIdx.x;
    int v = (t < nb) ? p[t] : 0;
    sh[t] = v;
    __syncthreads();
    for (int o = 1; o < 512; o <<= 1) {
        int x = (t >= o) ? sh[t - o] : 0;
        __syncthreads();
        sh[t] += x;
        __syncthreads();
    }
    if (t < nb) p[t] = sh[t] - v;  // exclusive
}

__global__ void scan_final_kernel(const int* __restrict__ cnt, const int* __restrict__ part,
                                  int* __restrict__ off, int* __restrict__ pos) {
    __shared__ int sh[256];
    const int* c = cnt + blockIdx.y * NN;
    const int* p = part + blockIdx.y * 512;
    int* of = off + blockIdx.y * NN;
    int* ps = pos + blockIdx.y * NN;
    int t = threadIdx.x;
    int i = blockIdx.x * 256 + t;
    int v = (i < NN) ? c[i] : 0;
    sh[t] = v;
    __syncthreads();
    for (int o = 1; o < 256; o <<= 1) {
        int x = (t >= o) ? sh[t - o] : 0;
        __syncthreads();
        sh[t] += x;
        __syncthreads();
    }
    if (i < NN) {
        int e = sh[t] - v + p[blockIdx.x];
        of[i] = e;
        ps[i] = e;
    }
}

__global__ void build_csr_kernel(const int* __restrict__ e0, const int* __restrict__ e1,
                                 int E, int* __restrict__ pos,
                                 int* __restrict__ c0, int* __restrict__ c1) {
    int t = blockIdx.y;
    const int* edge = t ? e1 : e0;
    int* ps = pos + t * NN;
    int* csr = t ? c1 : c0;
    int e = blockIdx.x * blockDim.x + threadIdx.x;
    if (e < E) {
        int s = edge[e];
        int d = edge[E + e];
        int idx = atomicAdd(&ps[d], 1);
        csr[idx] = s;
    }
}

// ---------------- gather-mean aggregation (layer 0, C=128), dual via gridDim.y ----------------
__global__ void gather_mean_kernel(const float* __restrict__ fA, const int* __restrict__ csrA, float* __restrict__ oA,
                                   const float* __restrict__ fB, const int* __restrict__ csrB, float* __restrict__ oB,
                                   const int* __restrict__ off, const int* __restrict__ cnt) {
    constexpr int G = 32;
    const int t = blockIdx.y;
    const float* feat = t ? fB : fA;
    const int* csr = t ? csrB : csrA;
    float* out = t ? oB : oA;
    const int* of = off + t * NN;
    const int* cn = cnt + t * NN;

    int gid = (int)((blockIdx.x * (size_t)blockDim.x + threadIdx.x) / G);
    if (gid >= NN) return;
    const int c4 = (threadIdx.x & (G - 1)) * 4;
    const int beg = __ldg(&of[gid]);
    const int deg = __ldg(&cn[gid]);

    float4 a0 = make_float4(0.f, 0.f, 0.f, 0.f);
    float4 a1 = make_float4(0.f, 0.f, 0.f, 0.f);
    float4 a2 = make_float4(0.f, 0.f, 0.f, 0.f);
    float4 a3 = make_float4(0.f, 0.f, 0.f, 0.f);
    int e = 0;
    for (; e + 3 < deg; e += 4) {
        int s0 = __ldg(&csr[beg + e]);
        int s1 = __ldg(&csr[beg + e + 1]);
        int s2 = __ldg(&csr[beg + e + 2]);
        int s3 = __ldg(&csr[beg + e + 3]);
        float4 v0 = *(const float4*)(feat + (size_t)s0 * HD + c4);
        float4 v1 = *(const float4*)(feat + (size_t)s1 * HD + c4);
        float4 v2 = *(const float4*)(feat + (size_t)s2 * HD + c4);
        float4 v3 = *(const float4*)(feat + (size_t)s3 * HD + c4);
        a0.x += v0.x; a0.y += v0.y; a0.z += v0.z; a0.w += v0.w;
        a1.x += v1.x; a1.y += v1.y; a1.z += v1.z; a1.w += v1.w;
        a2.x += v2.x; a2.y += v2.y; a2.z += v2.z; a2.w += v2.w;
        a3.x += v3.x; a3.y += v3.y; a3.z += v3.z; a3.w += v3.w;
    }
    for (; e < deg; e++) {
        int s0 = __ldg(&csr[beg + e]);
        float4 v0 = *(const float4*)(feat + (size_t)s0 * HD + c4);
        a0.x += v0.x; a0.y += v0.y; a0.z += v0.z; a0.w += v0.w;
    }
    const float sc = 1.0f / fmaxf((float)deg, 1.0f);
    float4 r;
    r.x = (a0.x + a1.x + a2.x + a3.x) * sc;
    r.y = (a0.y + a1.y + a2.y + a3.y) * sc;
    r.z = (a0.z + a1.z + a2.z + a3.z) * sc;
    r.w = (a0.w + a1.w + a2.w + a3.w) * sc;
    *(float4*)(out + (size_t)gid * HD + c4) = r;
}

// ---------------- fused layer-1 gather + final LN ----------------
// warp per dst row: acc = mean over neighbors of tmp_src[:, :64], v = acc + tmp_dst[row, 64:] + bias, out = LN(v)
struct FSide { const float* tmp_src; const float* tmp_dst; const int* csr;
               const float* bias; const float* g; const float* b; float* out; };
__global__ void final_fused_kernel(FSide f0, FSide f1, const int* __restrict__ off, const int* __restrict__ cnt) {
    const int t = blockIdx.y;
    FSide s = t ? f1 : f0;
    const int* of = off + t * NN;
    const int* cn = cnt + t * NN;
    const int warp = threadIdx.x >> 5;
    const int lane = threadIdx.x & 31;
    const int row = blockIdx.x * 8 + warp;
    if (row >= NN) return;
    const int c = lane * 2;
    const int beg = __ldg(&of[row]);
    const int deg = __ldg(&cn[row]);

    float x0 = 0.f, y0 = 0.f, x1 = 0.f, y1 = 0.f;
    int e = 0;
    for (; e + 1 < deg; e += 2) {
        int s0 = __ldg(&s.csr[beg + e]);
        int s1 = __ldg(&s.csr[beg + e + 1]);
        float2 v0 = *(const float2*)(s.tmp_src + (size_t)s0 * HD + c);
        float2 v1 = *(const float2*)(s.tmp_src + (size_t)s1 * HD + c);
        x0 += v0.x; y0 += v0.y;
        x1 += v1.x; y1 += v1.y;
    }
    if (e < deg) {
        int s0 = __ldg(&s.csr[beg + e]);
        float2 v0 = *(const float2*)(s.tmp_src + (size_t)s0 * HD + c);
        x0 += v0.x; y0 += v0.y;
    }
    const float sc = 1.0f / fmaxf((float)deg, 1.0f);
    float2 rv = *(const float2*)(s.tmp_dst + (size_t)row * HD + 64 + c);
    float2 bv = __ldg((const float2*)(s.bias + c));
    float v0 = (x0 + x1) * sc + rv.x + bv.x;
    float v1 = (y0 + y1) * sc + rv.y + bv.y;

    float s1v = v0 + v1;
    float s2v = v0 * v0 + v1 * v1;
#pragma unroll
    for (int o = 16; o > 0; o >>= 1) {
        s1v += __shfl_xor_sync(0xFFFFFFFFu, s1v, o);
        s2v += __shfl_xor_sync(0xFFFFFFFFu, s2v, o);
    }
    float mean = s1v * (1.0f / 64.0f);
    float var = s2v * (1.0f / 64.0f) - mean * mean;
    float rstd = rsqrtf(var + 1e-5f);
    float2 gv = __ldg((const float2*)(s.g + c));
    float2 bb = __ldg((const float2*)(s.b + c));
    float2 o2;
    o2.x = (v0 - mean) * rstd * gv.x + bb.x;
    o2.y = (v1 - mean) * rstd * gv.y + bb.y;
    *(float2*)(s.out + (size_t)row * 64 + c) = o2;
}

// weight transpose + bf16 hi/lo split: W [K,N] fp32 -> Wt [N,Kpad] bf16 (hi,lo), zero pad
struct WCon { const float* w; __nv_bfloat16* h; __nv_bfloat16* l; int K, N, Kpad; };
struct WCon10 { WCon s[10]; };
__global__ void wconv_kernel(WCon10 P) {
    WCon w = P.s[blockIdx.y];
    int idx = blockIdx.x * blockDim.x + threadIdx.x;
    if (idx >= w.N * w.Kpad) return;
    int n = idx / w.Kpad, k = idx % w.Kpad;
    float x = (k < w.K) ? w.w[(size_t)k * w.N + n] : 0.0f;
    __nv_bfloat16 h = __float2bfloat16(x);
    w.h[idx] = h;
    w.l[idx] = __float2bfloat16(x - __bfloat162float(h));
}

// ---------------- HMMA (mma.sync) GEMM, BN=128, 4x2 warp tiling, paired via gridDim.y ----------------
#define BN 128

struct GSide {
    const float* A1; const __nv_bfloat16* W1h; const __nv_bfloat16* W1l; int K1; int K1pad;
    const float* A2; const __nv_bfloat16* W2h; const __nv_bfloat16* W2l; int K2; int K2pad;
    const float* bias; const float* gamma; const float* beta; float* out;
};

template <bool FUSE2, bool DO_LN, bool DO_RELU>
__global__ __launch_bounds__(256, 2)
void mma_gemm(GSide s0, GSide s1, int M) {
    const GSide& S = blockIdx.y ? s1 : s0;

    extern __shared__ char smem[];
    const uint32_t sb = smem_u32(smem);
    const uint32_t aHiB = sb;
    const uint32_t aLoB = sb + 16384;
    const uint32_t bHiB = sb + 32768;
    const uint32_t bLoB = sb + 49152;

    const int tid = threadIdx.x;
    const int warp = tid >> 5;
    const int lane = tid & 31;
    const int wm = warp & 3;
    const int wn = warp >> 2;
    const int r0 = blockIdx.x * 128;

    float acc[2][8][4];
#pragma unroll
    for (int mt = 0; mt < 2; mt++)
#pragma unroll
        for (int nt = 0; nt < 8; nt++)
#pragma unroll
            for (int j = 0; j < 4; j++) acc[mt][nt][j] = 0.0f;

    // staging mapping
    const int ar = tid >> 1;
    const int acb = (tid & 1) * 32;
    const int bn = tid >> 1;
    const int bq = tid & 1;

    // compute-phase lane constants
    const uint32_t a_off0 = (uint32_t)(wm * 32 + (lane & 15)) * 128;
    const uint32_t a_off1 = a_off0 + 16 * 128;
    const uint32_t a_xm = (lane & 7) * 16;
    const uint32_t a_khalf = ((lane >> 4) & 1) * 16;
    const uint32_t b_rowbase = (uint32_t)(wn * 64 + (lane & 7) + ((lane >> 4) & 1) * 8) * 128;
    const uint32_t b_xm = (lane & 7) * 16;
    const uint32_t b_khalf = ((lane >> 3) & 1) * 16;

    const int nch1 = S.K1pad >> 6;
    const int nch = nch1 + (FUSE2 ? (S.K2pad >> 6) : 0);

    for (int c = 0; c < nch; c++) {
        if (c) __syncthreads();

        const float* A;
        const __nv_bfloat16 *Wh, *Wl;
        int k0, K, Kpad;
        if (!FUSE2 || c < nch1) { A = S.A1; Wh = S.W1h; Wl = S.W1l; k0 = c * 64; K = S.K1; Kpad = S.K1pad; }
        else                    { A = S.A2; Wh = S.W2h; Wl = S.W2l; k0 = (c - nch1) * 64; K = S.K2; Kpad = S.K2pad; }

        // ---- stage A (fp32 -> bf16 hi/lo, swizzled) ----
        {
            const int grow = r0 + ar;
            const float* arow = A + (size_t)grow * K;
#pragma unroll
            for (int i = 0; i < 4; i++) {
                const int cc = acb + i * 8;
                float x[8];
#pragma unroll
                for (int j = 0; j < 8; j++) x[j] = 0.0f;
                if (grow < M && (k0 + cc) < K) {
                    float4 v0 = *(const float4*)(arow + k0 + cc);
                    float4 v1 = *(const float4*)(arow + k0 + cc + 4);
                    x[0] = v0.x; x[1] = v0.y; x[2] = v0.z; x[3] = v0.w;
                    x[4] = v1.x; x[5] = v1.y; x[6] = v1.z; x[7] = v1.w;
                }
                uint32_t hi[4], lo[4];
#pragma unroll
                for (int j = 0; j < 4; j++) {
                    __nv_bfloat16 h0 = __float2bfloat16(x[2 * j]);
                    __nv_bfloat16 h1 = __float2bfloat16(x[2 * j + 1]);
                    float l0 = x[2 * j] - __bfloat162float(h0);
                    float l1 = x[2 * j + 1] - __bfloat162float(h1);
                    __nv_bfloat16 e0 = __float2bfloat16(l0);
                    __nv_bfloat16 e1 = __float2bfloat16(l1);
                    hi[j] = (uint32_t)__bfloat16_as_ushort(h0) | ((uint32_t)__bfloat16_as_ushort(h1) << 16);
                    lo[j] = (uint32_t)__bfloat16_as_ushort(e0) | ((uint32_t)__bfloat16_as_ushort(e1) << 16);
                }
                const uint32_t off = SWZ(ar * 128 + cc * 2);
                asm volatile("st.shared.v4.b32 [%0], {%1, %2, %3, %4};" :: "r"(aHiB + off), "r"(hi[0]), "r"(hi[1]), "r"(hi[2]), "r"(hi[3]) : "memory");
                asm volatile("st.shared.v4.b32 [%0], {%1, %2, %3, %4};" :: "r"(aLoB + off), "r"(lo[0]), "r"(lo[1]), "r"(lo[2]), "r"(lo[3]) : "memory");
            }
        }
        // ---- stage B (pre-split bf16 [128, Kpad], swizzled copy) ----
        {
#pragma unroll
            for (int i = 0; i < 4; i++) {
                const int ck = bq * 32 + i * 8;
                const size_t so = (size_t)bn * Kpad + k0 + ck;
                uint4 vh = *(const uint4*)(Wh + so);
                uint4 vl = *(const uint4*)(Wl + so);
                const uint32_t off = SWZ(bn * 128 + ck * 2);
                asm volatile("st.shared.v4.b32 [%0], {%1, %2, %3, %4};" :: "r"(bHiB + off), "r"(vh.x), "r"(vh.y), "r"(vh.z), "r"(vh.w) : "memory");
                asm volatile("st.shared.v4.b32 [%0], {%1, %2, %3, %4};" :: "r"(bLoB + off), "r"(vl.x), "r"(vl.y), "r"(vl.z), "r"(vl.w) : "memory");
            }
        }
        __syncthreads();

        // ---- compute ----
#pragma unroll
        for (int ks = 0; ks < 4; ks++) {
            const uint32_t akb = ((uint32_t)(ks * 32) + a_khalf) ^ a_xm;
            uint32_t ah[2][4], al[2][4];
            ldm4(ah[0], aHiB + a_off0 + akb);
            ldm4(ah[1], aHiB + a_off1 + akb);
            ldm4(al[0], aLoB + a_off0 + akb);
            ldm4(al[1], aLoB + a_off1 + akb);
            const uint32_t bkb = ((uint32_t)(ks * 32) + b_khalf) ^ b_xm;
#pragma unroll
            for (int j = 0; j < 4; j++) {
                uint32_t bh[4], bl[4];
                const uint32_t boff = b_rowbase + (uint32_t)j * 2048;
                ldm4(bh, bHiB + boff + bkb);
                ldm4(bl, bLoB + boff + bkb);
#pragma unroll
                for (int mt = 0; mt < 2; mt++) {
                    mma_bf16(acc[mt][2 * j],     ah[mt], bh[0], bh[1]);
                    mma_bf16(acc[mt][2 * j],     ah[mt], bl[0], bl[1]);
                    mma_bf16(acc[mt][2 * j],     al[mt], bh[0], bh[1]);
                    mma_bf16(acc[mt][2 * j + 1], ah[mt], bh[2], bh[3]);
                    mma_bf16(acc[mt][2 * j + 1], ah[mt], bl[2], bl[3]);
                    mma_bf16(acc[mt][2 * j + 1], al[mt], bh[2], bh[3]);
                }
            }
        }
    }

    // ---- epilogue ----
    const int rq = lane >> 2;
    const int cq = (lane & 3) * 2;

    if (S.bias) {
#pragma unroll
        for (int nt = 0; nt < 8; nt++) {
            float2 bv = __ldg((const float2*)(S.bias + wn * 64 + nt * 8 + cq));
#pragma unroll
            for (int mt = 0; mt < 2; mt++) {
                acc[mt][nt][0] += bv.x; acc[mt][nt][1] += bv.y;
                acc[mt][nt][2] += bv.x; acc[mt][nt][3] += bv.y;
            }
        }
    }
    if (DO_LN) {
        float s1[2][2], s2[2][2];
#pragma unroll
        for (int mt = 0; mt < 2; mt++)
#pragma unroll
            for (int h = 0; h < 2; h++) { s1[mt][h] = 0.f; s2[mt][h] = 0.f; }
#pragma unroll
        for (int mt = 0; mt < 2; mt++)
#pragma unroll
            for (int nt = 0; nt < 8; nt++) {
                s1[mt][0] += acc[mt][nt][0] + acc[mt][nt][1];
                s2[mt][0] += acc[mt][nt][0] * acc[mt][nt][0] + acc[mt][nt][1] * acc[mt][nt][1];
                s1[mt][1] += acc[mt][nt][2] + acc[mt][nt][3];
                s2[mt][1] += acc[mt][nt][2] * acc[mt][nt][2] + acc[mt][nt][3] * acc[mt][nt][3];
            }
#pragma unroll
        for (int o = 1; o < 4; o <<= 1) {
#pragma unroll
            for (int mt = 0; mt < 2; mt++)
#pragma unroll
                for (int h = 0; h < 2; h++) {
                    s1[mt][h] += __shfl_xor_sync(0xFFFFFFFFu, s1[mt][h], o);
                    s2[mt][h] += __shfl_xor_sync(0xFFFFFFFFu, s2[mt][h], o);
                }
        }
        float* sc = (float*)smem;
        __syncthreads();
        if ((lane & 3) == 0) {
#pragma unroll
            for (int mt = 0; mt < 2; mt++)
#pragma unroll
                for (int h = 0; h < 2; h++) {
                    int rl = wm * 32 + mt * 16 + h * 8 + rq;
                    sc[wn * 128 + rl] = s1[mt][h];
                    sc[256 + wn * 128 + rl] = s2[mt][h];
                }
        }
        __syncthreads();
#pragma unroll
        for (int mt = 0; mt < 2; mt++)
#pragma unroll
            for (int h = 0; h < 2; h++) {
                int rl = wm * 32 + mt * 16 + h * 8 + rq;
                float S1 = sc[rl] + sc[128 + rl];
                float S2 = sc[256 + rl] + sc[384 + rl];
                float mean = S1 * (1.0f / 128.0f);
                float var = S2 * (1.0f / 128.0f) - mean * mean;
                float rstd = rsqrtf(var + 1e-5f);
                s1[mt][h] = mean;
                s2[mt][h] = rstd;
            }
#pragma unroll
        for (int nt = 0; nt < 8; nt++) {
            float2 g = __ldg((const float2*)(S.gamma + wn * 64 + nt * 8 + cq));
            float2 b = __ldg((const float2*)(S.beta + wn * 64 + nt * 8 + cq));
#pragma unroll
            for (int mt = 0; mt < 2; mt++) {
                acc[mt][nt][0] = (acc[mt][nt][0] - s1[mt][0]) * s2[mt][0] * g.x + b.x;
                acc[mt][nt][1] = (acc[mt][nt][1] - s1[mt][0]) * s2[mt][0] * g.y + b.y;
                acc[mt][nt][2] = (acc[mt][nt][2] - s1[mt][1]) * s2[mt][1] * g.x + b.x;
                acc[mt][nt][3] = (acc[mt][nt][3] - s1[mt][1]) * s2[mt][1] * g.y + b.y;
            }
        }
    }
    if (DO_RELU) {
#pragma unroll
        for (int mt = 0; mt < 2; mt++)
#pragma unroll
            for (int nt = 0; nt < 8; nt++)
#pragma unroll
                for (int j = 0; j < 4; j++) acc[mt][nt][j] = fmaxf(acc[mt][nt][j], 0.0f);
    }
#pragma unroll
    for (int mt = 0; mt < 2; mt++)
#pragma unroll
        for (int h = 0; h < 2; h++) {
            int row = r0 + wm * 32 + mt * 16 + h * 8 + rq;
            if (row < M) {
#pragma unroll
                for (int nt = 0; nt < 8; nt++)
                    *(float2*)(S.out + (size_t)row * BN + wn * 64 + nt * 8 + cq) =
                        make_float2(acc[mt][nt][2 * h], acc[mt][nt][2 * h + 1]);
            }
        }
}

// ---------------- host launcher ----------------
extern "C" void kernel_launch(void* const* d_in, const int* in_sizes, int n_in,
                              void* d_out, int out_size) {
    const float* x_user = (const float*)d_in[0];
    const float* x_item = (const float*)d_in[1];
    const int* edge_ui = (const int*)d_in[2];
    const int* edge_iu = (const int*)d_in[3];
    const float* Wp_u = (const float*)d_in[4];
    const float* bp_u = (const float*)d_in[5];
    const float* Wp_i = (const float*)d_in[6];
    const float* bp_i = (const float*)d_in[7];
    const float* Wl0_ui = (const float*)d_in[8];
    const float* bl0_ui = (const float*)d_in[9];
    const float* Wr0_ui = (const float*)d_in[10];
    const float* Wl0_iu = (const float*)d_in[11];
    const float* bl0_iu = (const float*)d_in[12];
    const float* Wr0_iu = (const float*)d_in[13];
    const float* g0_u = (const float*)d_in[14];
    const float* b0_u = (const float*)d_in[15];
    const float* g0_i = (const float*)d_in[16];
    const float* b0_i = (const float*)d_in[17];
    const float* Wl1_ui = (const float*)d_in[18];
    const float* bl1_ui = (const float*)d_in[19];
    const float* Wr1_ui = (const float*)d_in[20];
    const float* Wl1_iu = (const float*)d_in[21];
    const float* bl1_iu = (const float*)d_in[22];
    const float* Wr1_iu = (const float*)d_in[23];
    const float* g1_u = (const float*)d_in[24];
    const float* b1_u = (const float*)d_in[25];
    const float* g1_i = (const float*)d_in[26];
    const float* b1_i = (const float*)d_in[27];

    const int E = in_sizes[2] / 2;

    float *hu, *hi, *agg_u, *agg_i, *hu1, *hi1;
    int *cnt, *off, *pos, *csr_iu, *csr_ui, *part;
    cudaGetSymbolAddress((void**)&hu, g_hu);
    cudaGetSymbolAddress((void**)&hi, g_hi);
    cudaGetSymbolAddress((void**)&agg_u, g_agg_u);
    cudaGetSymbolAddress((void**)&agg_i, g_agg_i);
    cudaGetSymbolAddress((void**)&hu1, g_hu1);
    cudaGetSymbolAddress((void**)&hi1, g_hi1);
    cudaGetSymbolAddress((void**)&cnt, g_cnt);
    cudaGetSymbolAddress((void**)&off, g_off);
    cudaGetSymbolAddress((void**)&pos, g_pos);
    cudaGetSymbolAddress((void**)&csr_iu, g_csr_iu);
    cudaGetSymbolAddress((void**)&csr_ui, g_csr_ui);
    cudaGetSymbolAddress((void**)&part, g_part);

    __nv_bfloat16 *wpu_h, *wpu_l, *wpi_h, *wpi_l;
    __nv_bfloat16 *wl0ui_h, *wl0ui_l, *wr0ui_h, *wr0ui_l, *wl0iu_h, *wl0iu_l, *wr0iu_h, *wr0iu_l;
    __nv_bfloat16 *w1u_h, *w1u_l, *w1i_h, *w1i_l;
    cudaGetSymbolAddress((void**)&wpu_h, g_wpu_h);   cudaGetSymbolAddress((void**)&wpu_l, g_wpu_l);
    cudaGetSymbolAddress((void**)&wpi_h, g_wpi_h);   cudaGetSymbolAddress((void**)&wpi_l, g_wpi_l);
    cudaGetSymbolAddress((void**)&wl0ui_h, g_wl0ui_h); cudaGetSymbolAddress((void**)&wl0ui_l, g_wl0ui_l);
    cudaGetSymbolAddress((void**)&wr0ui_h, g_wr0ui_h); cudaGetSymbolAddress((void**)&wr0ui_l, g_wr0ui_l);
    cudaGetSymbolAddress((void**)&wl0iu_h, g_wl0iu_h); cudaGetSymbolAddress((void**)&wl0iu_l, g_wl0iu_l);
    cudaGetSymbolAddress((void**)&wr0iu_h, g_wr0iu_h); cudaGetSymbolAddress((void**)&wr0iu_l, g_wr0iu_l);
    cudaGetSymbolAddress((void**)&w1u_h, g_w1u_h);   cudaGetSymbolAddress((void**)&w1u_l, g_w1u_l);
    cudaGetSymbolAddress((void**)&w1i_h, g_w1i_h);   cudaGetSymbolAddress((void**)&w1i_l, g_w1i_l);

    float* out_u = (float*)d_out;
    float* out_i = (float*)d_out + (size_t)NN * OD;

    const int SM = 65536;
    cudaFuncSetAttribute(mma_gemm<false, false, true>, cudaFuncAttributeMaxDynamicSharedMemorySize, SM);
    cudaFuncSetAttribute(mma_gemm<true, true, true>, cudaFuncAttributeMaxDynamicSharedMemorySize, SM);
    cudaFuncSetAttribute(mma_gemm<false, false, false>, cudaFuncAttributeMaxDynamicSharedMemorySize, SM);

    const int GM = (NN + 127) / 128;

    // launch order engineered so the 6th kernel launch is the proj GEMM pair (for ncu -s 5)
    // 0: zero_cnt, 1: wconv, 2: count, 3: scan_part, 4: scan_partials, 5: PROJ GEMM PAIR,
    // 6: scan_final, 7: build_csr, 8: gather, 9: layer0 pair, 10: layer1 pair, 11: final fused
    zero_cnt_kernel<<<(2 * NN + 255) / 256, 256>>>(cnt);

    {
        WCon10 P;
        P.s[0] = { Wp_u,   wpu_h,   wpu_l,   FU, HD, 128 };
        P.s[1] = { Wp_i,   wpi_h,   wpi_l,   FI, HD, 192 };
        P.s[2] = { Wl0_ui, wl0ui_h, wl0ui_l, HD, HD, 128 };
        P.s[3] = { Wr0_ui, wr0ui_h, wr0ui_l, HD, HD, 128 };
        P.s[4] = { Wl0_iu, wl0iu_h, wl0iu_l, HD, HD, 128 };
        P.s[5] = { Wr0_iu, wr0iu_h, wr0iu_l, HD, HD, 128 };
        P.s[6] = { Wl1_ui, w1u_h,             w1u_l,             HD, OD, 128 };
        P.s[7] = { Wr1_iu, w1u_h + 64 * 128,  w1u_l + 64 * 128,  HD, OD, 128 };
        P.s[8] = { Wl1_iu, w1i_h,             w1i_l,             HD, OD, 128 };
        P.s[9] = { Wr1_ui, w1i_h + 64 * 128,  w1i_l + 64 * 128,  HD, OD, 128 };
        dim3 g((192 * 128 + 255) / 256, 10);
        wconv_kernel<<<g, 256>>>(P);
    }

    {
        dim3 ge((E + 255) / 256, 2);
        count_kernel<<<ge, 256>>>(edge_iu + E, edge_ui + E, E, cnt);
        scan_part_kernel<<<dim3(NBLK, 2), 256>>>(cnt, part);
        scan_partials_kernel<<<dim3(1, 2), 512>>>(part, NBLK);
    }

    // input projection + ReLU (merged pair)
    {
        GSide su = { x_user, wpu_h, wpu_l, FU, 128, nullptr, nullptr, nullptr, 0, 0,
                     bp_u, nullptr, nullptr, hu };
        GSide si = { x_item, wpi_h, wpi_l, FI, 192, nullptr, nullptr, nullptr, 0, 0,
                     bp_i, nullptr, nullptr, hi };
        mma_gemm<false, false, true><<<dim3(GM, 2), 256, SM>>>(su, si, NN);
    }

    {
        dim3 ge((E + 255) / 256, 2);
        scan_final_kernel<<<dim3(NBLK, 2), 256>>>(cnt, part, off, pos);
        build_csr_kernel<<<ge, 256>>>(edge_iu, edge_ui, E, pos, csr_iu, csr_ui);
    }

    // layer 0 aggregation. t=0: agg_u <- hi via csr_iu; t=1: agg_i <- hu via csr_ui
    {
        const long tot = (long)NN * 32;
        dim3 gg((unsigned)((tot + 255) / 256), 2);
        gather_mean_kernel<<<gg, 256>>>(hi, csr_iu, agg_u, hu, csr_ui, agg_i, off, cnt);
    }

    // layer 0 fused dual-GEMM + bias + LN + ReLU (merged pair)
    {
        GSide si = { agg_i, wl0ui_h, wl0ui_l, HD, 128, hi, wr0ui_h, wr0ui_l, HD, 128,
                     bl0_ui, g0_i, b0_i, hi1 };
        GSide su = { agg_u, wl0iu_h, wl0iu_l, HD, 128, hu, wr0iu_h, wr0iu_l, HD, 128,
                     bl0_iu, g0_u, b0_u, hu1 };
        mma_gemm<true, true, true><<<dim3(GM, 2), 256, SM>>>(si, su, NN);
    }

    // layer 1 combined GEMM pair: tmp = h1 @ [Wl1 | Wr1]  (cols 0-63 proj, 64-127 root)
    float* tmp_u = agg_u;
    float* tmp_i = agg_i;
    {
        GSide su = { hu1, w1u_h, w1u_l, HD, 128, nullptr, nullptr, nullptr, 0, 0,
                     nullptr, nullptr, nullptr, tmp_u };
        GSide si = { hi1, w1i_h, w1i_l, HD, 128, nullptr, nullptr, nullptr, 0, 0,
                     nullptr, nullptr, nullptr, tmp_i };
        mma_gemm<false, false, false><<<dim3(GM, 2), 256, SM>>>(su, si, NN);
    }

    // fused layer-1 gather + final LN. t=0: out_u from tmp_i via csr_iu; t=1: out_i from tmp_u via csr_ui
    {
        FSide fu = { tmp_i, tmp_u, csr_iu, bl1_iu, g1_u, b1_u, out_u };
        FSide fi = { tmp_u, tmp_i, csr_ui, bl1_ui, g1_i, b1_i, out_i };
        dim3 gf((NN + 7) / 8, 2);
        final_fused_kernel<<<gf, 256>>>(fu, fi, off, cnt);
    }

    (void)n_in; (void)out_size; (void)in_sizes;
}

// round 7
// speedup vs baseline: 4.0839x; 1.0650x over previous
#include <cuda_runtime.h>
#include <cuda_bf16.h>
#include <cstdint>

// ---------------- problem constants ----------------
#define NU 100000
#define NI 100000
#define NN 100000   // NU == NI
#define FU 96
#define FI 160
#define HD 128
#define OD 64
#define EMAX 600000
#define NBLK 391   // ceil(100000/256)

// ---------------- scratch (device globals) ----------------
__device__ float g_hu   [NN * HD];
__device__ float g_hi   [NN * HD];
__device__ float g_agg_u[NN * HD];   // reused as tmp_u (layer-1 [proj|root])
__device__ float g_agg_i[NN * HD];   // reused as tmp_i
__device__ float g_hu1  [NN * HD];
__device__ float g_hi1  [NN * HD];
__device__ int   g_cnt [2 * NN];
__device__ int   g_off [2 * NN];
__device__ int   g_pos [2 * NN];
__device__ int   g_csr_iu[EMAX];
__device__ int   g_csr_ui[EMAX];
__device__ int   g_part[2 * 512];

// transposed/split bf16 weights: layout [N rows, Kpad cols], zero padded
__device__ __nv_bfloat16 g_wpu_h[128 * 128],  g_wpu_l[128 * 128];
__device__ __nv_bfloat16 g_wpi_h[128 * 192],  g_wpi_l[128 * 192];
__device__ __nv_bfloat16 g_wl0ui_h[128 * 128], g_wl0ui_l[128 * 128];
__device__ __nv_bfloat16 g_wr0ui_h[128 * 128], g_wr0ui_l[128 * 128];
__device__ __nv_bfloat16 g_wl0iu_h[128 * 128], g_wl0iu_l[128 * 128];
__device__ __nv_bfloat16 g_wr0iu_h[128 * 128], g_wr0iu_l[128 * 128];
__device__ __nv_bfloat16 g_w1u_h[128 * 128],  g_w1u_l[128 * 128];   // [Wl1_ui | Wr1_iu]
__device__ __nv_bfloat16 g_w1i_h[128 * 128],  g_w1i_l[128 * 128];   // [Wl1_iu | Wr1_ui]

// ---------------- helpers ----------------
__device__ __forceinline__ uint32_t smem_u32(const void* p) {
    uint32_t a;
    asm("{ .reg .u64 t; cvta.to.shared.u64 t, %1; cvt.u32.u64 %0, t; }" : "=r"(a) : "l"(p));
    return a;
}
#define SWZ(x) ((x) ^ (((x) >> 3) & 0x70))

#define CPA16(dst, src) \
    asm volatile("cp.async.ca.shared.global [%0], [%1], 16;" :: "r"(dst), "l"(src) : "memory")
#define CPA_COMMIT() asm volatile("cp.async.commit_group;" ::: "memory")
#define CPA_WAIT1()  asm volatile("cp.async.wait_group 1;" ::: "memory")
#define CPA_WAIT0()  asm volatile("cp.async.wait_group 0;" ::: "memory")

__device__ __forceinline__ void ldm4(uint32_t* r, uint32_t addr) {
    asm volatile("ldmatrix.sync.aligned.m8n8.x4.shared.b16 {%0,%1,%2,%3}, [%4];"
        : "=r"(r[0]), "=r"(r[1]), "=r"(r[2]), "=r"(r[3]) : "r"(addr));
}
__device__ __forceinline__ void mma_bf16(float* c, const uint32_t* a, uint32_t b0, uint32_t b1) {
    asm volatile("mma.sync.aligned.m16n8k16.row.col.f32.bf16.bf16.f32 "
        "{%0,%1,%2,%3}, {%4,%5,%6,%7}, {%8,%9}, {%0,%1,%2,%3};"
        : "+f"(c[0]), "+f"(c[1]), "+f"(c[2]), "+f"(c[3])
        : "r"(a[0]), "r"(a[1]), "r"(a[2]), "r"(a[3]), "r"(b0), "r"(b1));
}

// ---------------- CSR build chain ----------------
__global__ void zero_cnt_kernel(int* __restrict__ cnt) {
    int i = blockIdx.x * blockDim.x + threadIdx.x;
    if (i < 2 * NN) cnt[i] = 0;
}

__global__ void count_kernel(const int* __restrict__ dst0, const int* __restrict__ dst1,
                             int E, int* __restrict__ cnt) {
    int t = blockIdx.y;
    const int* dst = t ? dst1 : dst0;
    int* c = cnt + t * NN;
    int e = blockIdx.x * blockDim.x + threadIdx.x;
    if (e < E) atomicAdd(&c[dst[e]], 1);
}

__global__ void scan_part_kernel(const int* __restrict__ cnt, int* __restrict__ part) {
    __shared__ int sh[256];
    const int* c = cnt + blockIdx.y * NN;
    int* p = part + blockIdx.y * 512;
    int i = blockIdx.x * 256 + threadIdx.x;
    sh[threadIdx.x] = (i < NN) ? c[i] : 0;
    __syncthreads();
    for (int s = 128; s > 0; s >>= 1) {
        if (threadIdx.x < s) sh[threadIdx.x] += sh[threadIdx.x + s];
        __syncthreads();
    }
    if (threadIdx.x == 0) p[blockIdx.x] = sh[0];
}

__global__ void scan_partials_kernel(int* __restrict__ part, int nb) {
    __shared__ int sh[512];
    int* p = part + blockIdx.y * 512;
    int t = threadIdx.x;
    int v = (t < nb) ? p[t] : 0;
    sh[t] = v;
    __syncthreads();
    for (int o = 1; o < 512; o <<= 1) {
        int x = (t >= o) ? sh[t - o] : 0;
        __syncthreads();
        sh[t] += x;
        __syncthreads();
    }
    if (t < nb) p[t] = sh[t] - v;  // exclusive
}

__global__ void scan_final_kernel(const int* __restrict__ cnt, const int* __restrict__ part,
                                  int* __restrict__ off, int* __restrict__ pos) {
    __shared__ int sh[256];
    const int* c = cnt + blockIdx.y * NN;
    const int* p = part + blockIdx.y * 512;
    int* of = off + blockIdx.y * NN;
    int* ps = pos + blockIdx.y * NN;
    int t = threadIdx.x;
    int i = blockIdx.x * 256 + t;
    int v = (i < NN) ? c[i] : 0;
    sh[t] = v;
    __syncthreads();
    for (int o = 1; o < 256; o <<= 1) {
        int x = (t >= o) ? sh[t - o] : 0;
        __syncthreads();
        sh[t] += x;
        __syncthreads();
    }
    if (i < NN) {
        int e = sh[t] - v + p[blockIdx.x];
        of[i] = e;
        ps[i] = e;
    }
}

__global__ void build_csr_kernel(const int* __restrict__ e0, const int* __restrict__ e1,
                                 int E, int* __restrict__ pos,
                                 int* __restrict__ c0, int* __restrict__ c1) {
    int t = blockIdx.y;
    const int* edge = t ? e1 : e0;
    int* ps = pos + t * NN;
    int* csr = t ? c1 : c0;
    int e = blockIdx.x * blockDim.x + threadIdx.x;
    if (e < E) {
        int s = edge[e];
        int d = edge[E + e];
        int idx = atomicAdd(&ps[d], 1);
        csr[idx] = s;
    }
}

// ---------------- gather-mean aggregation (layer 0, C=128), dual via gridDim.y ----------------
__global__ void gather_mean_kernel(const float* __restrict__ fA, const int* __restrict__ csrA, float* __restrict__ oA,
                                   const float* __restrict__ fB, const int* __restrict__ csrB, float* __restrict__ oB,
                                   const int* __restrict__ off, const int* __restrict__ cnt) {
    constexpr int G = 32;
    const int t = blockIdx.y;
    const float* feat = t ? fB : fA;
    const int* csr = t ? csrB : csrA;
    float* out = t ? oB : oA;
    const int* of = off + t * NN;
    const int* cn = cnt + t * NN;

    int gid = (int)((blockIdx.x * (size_t)blockDim.x + threadIdx.x) / G);
    if (gid >= NN) return;
    const int c4 = (threadIdx.x & (G - 1)) * 4;
    const int beg = __ldg(&of[gid]);
    const int deg = __ldg(&cn[gid]);

    float4 a0 = make_float4(0.f, 0.f, 0.f, 0.f);
    float4 a1 = make_float4(0.f, 0.f, 0.f, 0.f);
    float4 a2 = make_float4(0.f, 0.f, 0.f, 0.f);
    float4 a3 = make_float4(0.f, 0.f, 0.f, 0.f);
    int e = 0;
    for (; e + 3 < deg; e += 4) {
        int s0 = __ldg(&csr[beg + e]);
        int s1 = __ldg(&csr[beg + e + 1]);
        int s2 = __ldg(&csr[beg + e + 2]);
        int s3 = __ldg(&csr[beg + e + 3]);
        float4 v0 = *(const float4*)(feat + (size_t)s0 * HD + c4);
        float4 v1 = *(const float4*)(feat + (size_t)s1 * HD + c4);
        float4 v2 = *(const float4*)(feat + (size_t)s2 * HD + c4);
        float4 v3 = *(const float4*)(feat + (size_t)s3 * HD + c4);
        a0.x += v0.x; a0.y += v0.y; a0.z += v0.z; a0.w += v0.w;
        a1.x += v1.x; a1.y += v1.y; a1.z += v1.z; a1.w += v1.w;
        a2.x += v2.x; a2.y += v2.y; a2.z += v2.z; a2.w += v2.w;
        a3.x += v3.x; a3.y += v3.y; a3.z += v3.z; a3.w += v3.w;
    }
    for (; e < deg; e++) {
        int s0 = __ldg(&csr[beg + e]);
        float4 v0 = *(const float4*)(feat + (size_t)s0 * HD + c4);
        a0.x += v0.x; a0.y += v0.y; a0.z += v0.z; a0.w += v0.w;
    }
    const float sc = 1.0f / fmaxf((float)deg, 1.0f);
    float4 r;
    r.x = (a0.x + a1.x + a2.x + a3.x) * sc;
    r.y = (a0.y + a1.y + a2.y + a3.y) * sc;
    r.z = (a0.z + a1.z + a2.z + a3.z) * sc;
    r.w = (a0.w + a1.w + a2.w + a3.w) * sc;
    *(float4*)(out + (size_t)gid * HD + c4) = r;
}

// ---------------- fused layer-1 gather + final LN ----------------
struct FSide { const float* tmp_src; const float* tmp_dst; const int* csr;
               const float* bias; const float* g; const float* b; float* out; };
__global__ void final_fused_kernel(FSide f0, FSide f1, const int* __restrict__ off, const int* __restrict__ cnt) {
    const int t = blockIdx.y;
    FSide s = t ? f1 : f0;
    const int* of = off + t * NN;
    const int* cn = cnt + t * NN;
    const int warp = threadIdx.x >> 5;
    const int lane = threadIdx.x & 31;
    const int row = blockIdx.x * 8 + warp;
    if (row >= NN) return;
    const int c = lane * 2;
    const int beg = __ldg(&of[row]);
    const int deg = __ldg(&cn[row]);

    float x0 = 0.f, y0 = 0.f, x1 = 0.f, y1 = 0.f;
    int e = 0;
    for (; e + 1 < deg; e += 2) {
        int s0 = __ldg(&s.csr[beg + e]);
        int s1 = __ldg(&s.csr[beg + e + 1]);
        float2 v0 = *(const float2*)(s.tmp_src + (size_t)s0 * HD + c);
        float2 v1 = *(const float2*)(s.tmp_src + (size_t)s1 * HD + c);
        x0 += v0.x; y0 += v0.y;
        x1 += v1.x; y1 += v1.y;
    }
    if (e < deg) {
        int s0 = __ldg(&s.csr[beg + e]);
        float2 v0 = *(const float2*)(s.tmp_src + (size_t)s0 * HD + c);
        x0 += v0.x; y0 += v0.y;
    }
    const float sc = 1.0f / fmaxf((float)deg, 1.0f);
    float2 rv = *(const float2*)(s.tmp_dst + (size_t)row * HD + 64 + c);
    float2 bv = __ldg((const float2*)(s.bias + c));
    float v0 = (x0 + x1) * sc + rv.x + bv.x;
    float v1 = (y0 + y1) * sc + rv.y + bv.y;

    float s1v = v0 + v1;
    float s2v = v0 * v0 + v1 * v1;
#pragma unroll
    for (int o = 16; o > 0; o >>= 1) {
        s1v += __shfl_xor_sync(0xFFFFFFFFu, s1v, o);
        s2v += __shfl_xor_sync(0xFFFFFFFFu, s2v, o);
    }
    float mean = s1v * (1.0f / 64.0f);
    float var = s2v * (1.0f / 64.0f) - mean * mean;
    float rstd = rsqrtf(var + 1e-5f);
    float2 gv = __ldg((const float2*)(s.g + c));
    float2 bb = __ldg((const float2*)(s.b + c));
    float2 o2;
    o2.x = (v0 - mean) * rstd * gv.x + bb.x;
    o2.y = (v1 - mean) * rstd * gv.y + bb.y;
    *(float2*)(s.out + (size_t)row * 64 + c) = o2;
}

// weight transpose + bf16 hi/lo split
struct WCon { const float* w; __nv_bfloat16* h; __nv_bfloat16* l; int K, N, Kpad; };
struct WCon10 { WCon s[10]; };
__global__ void wconv_kernel(WCon10 P) {
    WCon w = P.s[blockIdx.y];
    int idx = blockIdx.x * blockDim.x + threadIdx.x;
    if (idx >= w.N * w.Kpad) return;
    int n = idx / w.Kpad, k = idx % w.Kpad;
    float x = (k < w.K) ? w.w[(size_t)k * w.N + n] : 0.0f;
    __nv_bfloat16 h = __float2bfloat16(x);
    w.h[idx] = h;
    w.l[idx] = __float2bfloat16(x - __bfloat162float(h));
}

// ---------------- HMMA (mma.sync) GEMM, BN=128, 4x2 warp tiling, paired via gridDim.y ----------------
// B tiles double-buffered via cp.async; A staged synchronously (fp32 -> bf16 hi/lo split).
#define BN 128

struct GSide {
    const float* A1; const __nv_bfloat16* W1h; const __nv_bfloat16* W1l; int K1; int K1pad;
    const float* A2; const __nv_bfloat16* W2h; const __nv_bfloat16* W2l; int K2; int K2pad;
    const float* bias; const float* gamma; const float* beta; float* out;
};

template <bool FUSE2, bool DO_LN, bool DO_RELU>
__global__ __launch_bounds__(256, 2)
void mma_gemm(GSide s0, GSide s1, int M) {
    const GSide& S = blockIdx.y ? s1 : s0;

    extern __shared__ char smem[];
    const uint32_t sb = smem_u32(smem);
    const uint32_t aHiB = sb;
    const uint32_t aLoB = sb + 16384;
    const uint32_t bBuf0 = sb + 32768;   // bHi at +0, bLo at +16384; buffer stride 32768

    const int tid = threadIdx.x;
    const int warp = tid >> 5;
    const int lane = tid & 31;
    const int wm = warp & 3;
    const int wn = warp >> 2;
    const int r0 = blockIdx.x * 128;

    float acc[2][8][4];
#pragma unroll
    for (int mt = 0; mt < 2; mt++)
#pragma unroll
        for (int nt = 0; nt < 8; nt++)
#pragma unroll
            for (int j = 0; j < 4; j++) acc[mt][nt][j] = 0.0f;

    // staging mapping
    const int ar = tid >> 1;
    const int acb = (tid & 1) * 32;
    const int bn = tid >> 1;
    const int bq = tid & 1;

    // compute-phase lane constants
    const uint32_t a_off0 = (uint32_t)(wm * 32 + (lane & 15)) * 128;
    const uint32_t a_off1 = a_off0 + 16 * 128;
    const uint32_t a_xm = (lane & 7) * 16;
    const uint32_t a_khalf = ((lane >> 4) & 1) * 16;
    const uint32_t b_rowbase = (uint32_t)(wn * 64 + (lane & 7) + ((lane >> 4) & 1) * 8) * 128;
    const uint32_t b_xm = (lane & 7) * 16;
    const uint32_t b_khalf = ((lane >> 3) & 1) * 16;

    const int nch1 = S.K1pad >> 6;
    const int nch = nch1 + (FUSE2 ? (S.K2pad >> 6) : 0);

    // chunk -> source mapping
    auto chunk_w = [&](int c, const __nv_bfloat16*& Wh, const __nv_bfloat16*& Wl, int& k0, int& Kpad) {
        if (!FUSE2 || c < nch1) { Wh = S.W1h; Wl = S.W1l; k0 = c * 64; Kpad = S.K1pad; }
        else                    { Wh = S.W2h; Wl = S.W2l; k0 = (c - nch1) * 64; Kpad = S.K2pad; }
    };
    auto issueB = [&](int c, int buf) {
        const __nv_bfloat16 *Wh, *Wl;
        int k0, Kpad;
        chunk_w(c, Wh, Wl, k0, Kpad);
        const uint32_t bH = bBuf0 + (uint32_t)buf * 32768;
        const uint32_t bL = bH + 16384;
#pragma unroll
        for (int i = 0; i < 4; i++) {
            const int ck = bq * 32 + i * 8;
            const size_t so = (size_t)bn * Kpad + k0 + ck;
            const uint32_t off = SWZ(bn * 128 + ck * 2);
            CPA16(bH + off, Wh + so);
            CPA16(bL + off, Wl + so);
        }
        CPA_COMMIT();
    };

    issueB(0, 0);

    for (int c = 0; c < nch; c++) {
        if (c) __syncthreads();

        const float* A;
        int k0, K;
        if (!FUSE2 || c < nch1) { A = S.A1; k0 = c * 64; K = S.K1; }
        else                    { A = S.A2; k0 = (c - nch1) * 64; K = S.K2; }

        // ---- stage A (fp32 -> bf16 hi/lo, swizzled) ----
        {
            const int grow = r0 + ar;
            const float* arow = A + (size_t)grow * K;
#pragma unroll
            for (int i = 0; i < 4; i++) {
                const int cc = acb + i * 8;
                float x[8];
#pragma unroll
                for (int j = 0; j < 8; j++) x[j] = 0.0f;
                if (grow < M && (k0 + cc) < K) {
                    float4 v0 = *(const float4*)(arow + k0 + cc);
                    float4 v1 = *(const float4*)(arow + k0 + cc + 4);
                    x[0] = v0.x; x[1] = v0.y; x[2] = v0.z; x[3] = v0.w;
                    x[4] = v1.x; x[5] = v1.y; x[6] = v1.z; x[7] = v1.w;
                }
                uint32_t hi[4], lo[4];
#pragma unroll
                for (int j = 0; j < 4; j++) {
                    __nv_bfloat16 h0 = __float2bfloat16(x[2 * j]);
                    __nv_bfloat16 h1 = __float2bfloat16(x[2 * j + 1]);
                    float l0 = x[2 * j] - __bfloat162float(h0);
                    float l1 = x[2 * j + 1] - __bfloat162float(h1);
                    __nv_bfloat16 e0 = __float2bfloat16(l0);
                    __nv_bfloat16 e1 = __float2bfloat16(l1);
                    hi[j] = (uint32_t)__bfloat16_as_ushort(h0) | ((uint32_t)__bfloat16_as_ushort(h1) << 16);
                    lo[j] = (uint32_t)__bfloat16_as_ushort(e0) | ((uint32_t)__bfloat16_as_ushort(e1) << 16);
                }
                const uint32_t off = SWZ(ar * 128 + cc * 2);
                asm volatile("st.shared.v4.b32 [%0], {%1, %2, %3, %4};" :: "r"(aHiB + off), "r"(hi[0]), "r"(hi[1]), "r"(hi[2]), "r"(hi[3]) : "memory");
                asm volatile("st.shared.v4.b32 [%0], {%1, %2, %3, %4};" :: "r"(aLoB + off), "r"(lo[0]), "r"(lo[1]), "r"(lo[2]), "r"(lo[3]) : "memory");
            }
        }

        // ---- prefetch next B, then wait for current B ----
        if (c + 1 < nch) {
            issueB(c + 1, (c + 1) & 1);
            CPA_WAIT1();
        } else {
            CPA_WAIT0();
        }
        __syncthreads();

        // ---- compute ----
        const uint32_t bHiC = bBuf0 + (uint32_t)(c & 1) * 32768;
        const uint32_t bLoC = bHiC + 16384;
#pragma unroll
        for (int ks = 0; ks < 4; ks++) {
            const uint32_t akb = ((uint32_t)(ks * 32) + a_khalf) ^ a_xm;
            uint32_t ah[2][4], al[2][4];
            ldm4(ah[0], aHiB + a_off0 + akb);
            ldm4(ah[1], aHiB + a_off1 + akb);
            ldm4(al[0], aLoB + a_off0 + akb);
            ldm4(al[1], aLoB + a_off1 + akb);
            const uint32_t bkb = ((uint32_t)(ks * 32) + b_khalf) ^ b_xm;
#pragma unroll
            for (int j = 0; j < 4; j++) {
                uint32_t bh[4], bl[4];
                const uint32_t boff = b_rowbase + (uint32_t)j * 2048;
                ldm4(bh, bHiC + boff + bkb);
                ldm4(bl, bLoC + boff + bkb);
#pragma unroll
                for (int mt = 0; mt < 2; mt++) {
                    mma_bf16(acc[mt][2 * j],     ah[mt], bh[0], bh[1]);
                    mma_bf16(acc[mt][2 * j],     ah[mt], bl[0], bl[1]);
                    mma_bf16(acc[mt][2 * j],     al[mt], bh[0], bh[1]);
                    mma_bf16(acc[mt][2 * j + 1], ah[mt], bh[2], bh[3]);
                    mma_bf16(acc[mt][2 * j + 1], ah[mt], bl[2], bl[3]);
                    mma_bf16(acc[mt][2 * j + 1], al[mt], bh[2], bh[3]);
                }
            }
        }
    }

    // ---- epilogue ----
    const int rq = lane >> 2;
    const int cq = (lane & 3) * 2;

    if (S.bias) {
#pragma unroll
        for (int nt = 0; nt < 8; nt++) {
            float2 bv = __ldg((const float2*)(S.bias + wn * 64 + nt * 8 + cq));
#pragma unroll
            for (int mt = 0; mt < 2; mt++) {
                acc[mt][nt][0] += bv.x; acc[mt][nt][1] += bv.y;
                acc[mt][nt][2] += bv.x; acc[mt][nt][3] += bv.y;
            }
        }
    }
    if (DO_LN) {
        float s1[2][2], s2[2][2];
#pragma unroll
        for (int mt = 0; mt < 2; mt++)
#pragma unroll
            for (int h = 0; h < 2; h++) { s1[mt][h] = 0.f; s2[mt][h] = 0.f; }
#pragma unroll
        for (int mt = 0; mt < 2; mt++)
#pragma unroll
            for (int nt = 0; nt < 8; nt++) {
                s1[mt][0] += acc[mt][nt][0] + acc[mt][nt][1];
                s2[mt][0] += acc[mt][nt][0] * acc[mt][nt][0] + acc[mt][nt][1] * acc[mt][nt][1];
                s1[mt][1] += acc[mt][nt][2] + acc[mt][nt][3];
                s2[mt][1] += acc[mt][nt][2] * acc[mt][nt][2] + acc[mt][nt][3] * acc[mt][nt][3];
            }
#pragma unroll
        for (int o = 1; o < 4; o <<= 1) {
#pragma unroll
            for (int mt = 0; mt < 2; mt++)
#pragma unroll
                for (int h = 0; h < 2; h++) {
                    s1[mt][h] += __shfl_xor_sync(0xFFFFFFFFu, s1[mt][h], o);
                    s2[mt][h] += __shfl_xor_sync(0xFFFFFFFFu, s2[mt][h], o);
                }
        }
        float* sc = (float*)smem;
        __syncthreads();
        if ((lane & 3) == 0) {
#pragma unroll
            for (int mt = 0; mt < 2; mt++)
#pragma unroll
                for (int h = 0; h < 2; h++) {
                    int rl = wm * 32 + mt * 16 + h * 8 + rq;
                    sc[wn * 128 + rl] = s1[mt][h];
                    sc[256 + wn * 128 + rl] = s2[mt][h];
                }
        }
        __syncthreads();
#pragma unroll
        for (int mt = 0; mt < 2; mt++)
#pragma unroll
            for (int h = 0; h < 2; h++) {
                int rl = wm * 32 + mt * 16 + h * 8 + rq;
                float S1 = sc[rl] + sc[128 + rl];
                float S2 = sc[256 + rl] + sc[384 + rl];
                float mean = S1 * (1.0f / 128.0f);
                float var = S2 * (1.0f / 128.0f) - mean * mean;
                float rstd = rsqrtf(var + 1e-5f);
                s1[mt][h] = mean;
                s2[mt][h] = rstd;
            }
#pragma unroll
        for (int nt = 0; nt < 8; nt++) {
            float2 g = __ldg((const float2*)(S.gamma + wn * 64 + nt * 8 + cq));
            float2 b = __ldg((const float2*)(S.beta + wn * 64 + nt * 8 + cq));
#pragma unroll
            for (int mt = 0; mt < 2; mt++) {
                acc[mt][nt][0] = (acc[mt][nt][0] - s1[mt][0]) * s2[mt][0] * g.x + b.x;
                acc[mt][nt][1] = (acc[mt][nt][1] - s1[mt][0]) * s2[mt][0] * g.y + b.y;
                acc[mt][nt][2] = (acc[mt][nt][2] - s1[mt][1]) * s2[mt][1] * g.x + b.x;
                acc[mt][nt][3] = (acc[mt][nt][3] - s1[mt][1]) * s2[mt][1] * g.y + b.y;
            }
        }
    }
    if (DO_RELU) {
#pragma unroll
        for (int mt = 0; mt < 2; mt++)
#pragma unroll
            for (int nt = 0; nt < 8; nt++)
#pragma unroll
                for (int j = 0; j < 4; j++) acc[mt][nt][j] = fmaxf(acc[mt][nt][j], 0.0f);
    }
#pragma unroll
    for (int mt = 0; mt < 2; mt++)
#pragma unroll
        for (int h = 0; h < 2; h++) {
            int row = r0 + wm * 32 + mt * 16 + h * 8 + rq;
            if (row < M) {
#pragma unroll
                for (int nt = 0; nt < 8; nt++)
                    *(float2*)(S.out + (size_t)row * BN + wn * 64 + nt * 8 + cq) =
                        make_float2(acc[mt][nt][2 * h], acc[mt][nt][2 * h + 1]);
            }
        }
}

// ---------------- host launcher ----------------
extern "C" void kernel_launch(void* const* d_in, const int* in_sizes, int n_in,
                              void* d_out, int out_size) {
    const float* x_user = (const float*)d_in[0];
    const float* x_item = (const float*)d_in[1];
    const int* edge_ui = (const int*)d_in[2];
    const int* edge_iu = (const int*)d_in[3];
    const float* Wp_u = (const float*)d_in[4];
    const float* bp_u = (const float*)d_in[5];
    const float* Wp_i = (const float*)d_in[6];
    const float* bp_i = (const float*)d_in[7];
    const float* Wl0_ui = (const float*)d_in[8];
    const float* bl0_ui = (const float*)d_in[9];
    const float* Wr0_ui = (const float*)d_in[10];
    const float* Wl0_iu = (const float*)d_in[11];
    const float* bl0_iu = (const float*)d_in[12];
    const float* Wr0_iu = (const float*)d_in[13];
    const float* g0_u = (const float*)d_in[14];
    const float* b0_u = (const float*)d_in[15];
    const float* g0_i = (const float*)d_in[16];
    const float* b0_i = (const float*)d_in[17];
    const float* Wl1_ui = (const float*)d_in[18];
    const float* bl1_ui = (const float*)d_in[19];
    const float* Wr1_ui = (const float*)d_in[20];
    const float* Wl1_iu = (const float*)d_in[21];
    const float* bl1_iu = (const float*)d_in[22];
    const float* Wr1_iu = (const float*)d_in[23];
    const float* g1_u = (const float*)d_in[24];
    const float* b1_u = (const float*)d_in[25];
    const float* g1_i = (const float*)d_in[26];
    const float* b1_i = (const float*)d_in[27];

    const int E = in_sizes[2] / 2;

    float *hu, *hi, *agg_u, *agg_i, *hu1, *hi1;
    int *cnt, *off, *pos, *csr_iu, *csr_ui, *part;
    cudaGetSymbolAddress((void**)&hu, g_hu);
    cudaGetSymbolAddress((void**)&hi, g_hi);
    cudaGetSymbolAddress((void**)&agg_u, g_agg_u);
    cudaGetSymbolAddress((void**)&agg_i, g_agg_i);
    cudaGetSymbolAddress((void**)&hu1, g_hu1);
    cudaGetSymbolAddress((void**)&hi1, g_hi1);
    cudaGetSymbolAddress((void**)&cnt, g_cnt);
    cudaGetSymbolAddress((void**)&off, g_off);
    cudaGetSymbolAddress((void**)&pos, g_pos);
    cudaGetSymbolAddress((void**)&csr_iu, g_csr_iu);
    cudaGetSymbolAddress((void**)&csr_ui, g_csr_ui);
    cudaGetSymbolAddress((void**)&part, g_part);

    __nv_bfloat16 *wpu_h, *wpu_l, *wpi_h, *wpi_l;
    __nv_bfloat16 *wl0ui_h, *wl0ui_l, *wr0ui_h, *wr0ui_l, *wl0iu_h, *wl0iu_l, *wr0iu_h, *wr0iu_l;
    __nv_bfloat16 *w1u_h, *w1u_l, *w1i_h, *w1i_l;
    cudaGetSymbolAddress((void**)&wpu_h, g_wpu_h);   cudaGetSymbolAddress((void**)&wpu_l, g_wpu_l);
    cudaGetSymbolAddress((void**)&wpi_h, g_wpi_h);   cudaGetSymbolAddress((void**)&wpi_l, g_wpi_l);
    cudaGetSymbolAddress((void**)&wl0ui_h, g_wl0ui_h); cudaGetSymbolAddress((void**)&wl0ui_l, g_wl0ui_l);
    cudaGetSymbolAddress((void**)&wr0ui_h, g_wr0ui_h); cudaGetSymbolAddress((void**)&wr0ui_l, g_wr0ui_l);
    cudaGetSymbolAddress((void**)&wl0iu_h, g_wl0iu_h); cudaGetSymbolAddress((void**)&wl0iu_l, g_wl0iu_l);
    cudaGetSymbolAddress((void**)&wr0iu_h, g_wr0iu_h); cudaGetSymbolAddress((void**)&wr0iu_l, g_wr0iu_l);
    cudaGetSymbolAddress((void**)&w1u_h, g_w1u_h);   cudaGetSymbolAddress((void**)&w1u_l, g_w1u_l);
    cudaGetSymbolAddress((void**)&w1i_h, g_w1i_h);   cudaGetSymbolAddress((void**)&w1i_l, g_w1i_l);

    float* out_u = (float*)d_out;
    float* out_i = (float*)d_out + (size_t)NN * OD;

    const int SM = 98304;  // A 32KB + B 2x32KB
    cudaFuncSetAttribute(mma_gemm<false, false, true>, cudaFuncAttributeMaxDynamicSharedMemorySize, SM);
    cudaFuncSetAttribute(mma_gemm<true, true, true>, cudaFuncAttributeMaxDynamicSharedMemorySize, SM);
    cudaFuncSetAttribute(mma_gemm<false, false, false>, cudaFuncAttributeMaxDynamicSharedMemorySize, SM);

    const int GM = (NN + 127) / 128;

    // fork a side stream for the CSR chain (independent of weights/proj)
    cudaStream_t sB;
    cudaEvent_t eFork, eJoin;
    cudaStreamCreateWithFlags(&sB, cudaStreamNonBlocking);
    cudaEventCreateWithFlags(&eFork, cudaEventDisableTiming);
    cudaEventCreateWithFlags(&eJoin, cudaEventDisableTiming);

    cudaEventRecord(eFork, 0);
    cudaStreamWaitEvent(sB, eFork, 0);

    // side stream: degree + CSR build
    {
        dim3 ge((E + 255) / 256, 2);
        zero_cnt_kernel<<<(2 * NN + 255) / 256, 256, 0, sB>>>(cnt);
        count_kernel<<<ge, 256, 0, sB>>>(edge_iu + E, edge_ui + E, E, cnt);
        scan_part_kernel<<<dim3(NBLK, 2), 256, 0, sB>>>(cnt, part);
        scan_partials_kernel<<<dim3(1, 2), 512, 0, sB>>>(part, NBLK);
        scan_final_kernel<<<dim3(NBLK, 2), 256, 0, sB>>>(cnt, part, off, pos);
        build_csr_kernel<<<ge, 256, 0, sB>>>(edge_iu, edge_ui, E, pos, csr_iu, csr_ui);
        cudaEventRecord(eJoin, sB);
    }

    // main stream: weight convert + projection GEMM pair
    {
        WCon10 P;
        P.s[0] = { Wp_u,   wpu_h,   wpu_l,   FU, HD, 128 };
        P.s[1] = { Wp_i,   wpi_h,   wpi_l,   FI, HD, 192 };
        P.s[2] = { Wl0_ui, wl0ui_h, wl0ui_l, HD, HD, 128 };
        P.s[3] = { Wr0_ui, wr0ui_h, wr0ui_l, HD, HD, 128 };
        P.s[4] = { Wl0_iu, wl0iu_h, wl0iu_l, HD, HD, 128 };
        P.s[5] = { Wr0_iu, wr0iu_h, wr0iu_l, HD, HD, 128 };
        P.s[6] = { Wl1_ui, w1u_h,             w1u_l,             HD, OD, 128 };
        P.s[7] = { Wr1_iu, w1u_h + 64 * 128,  w1u_l + 64 * 128,  HD, OD, 128 };
        P.s[8] = { Wl1_iu, w1i_h,             w1i_l,             HD, OD, 128 };
        P.s[9] = { Wr1_ui, w1i_h + 64 * 128,  w1i_l + 64 * 128,  HD, OD, 128 };
        dim3 g((192 * 128 + 255) / 256, 10);
        wconv_kernel<<<g, 256>>>(P);
    }
    {
        GSide su = { x_user, wpu_h, wpu_l, FU, 128, nullptr, nullptr, nullptr, 0, 0,
                     bp_u, nullptr, nullptr, hu };
        GSide si = { x_item, wpi_h, wpi_l, FI, 192, nullptr, nullptr, nullptr, 0, 0,
                     bp_i, nullptr, nullptr, hi };
        mma_gemm<false, false, true><<<dim3(GM, 2), 256, SM>>>(su, si, NN);
    }

    // join: gather needs CSR + proj outputs
    cudaStreamWaitEvent(0, eJoin, 0);

    // layer 0 aggregation. t=0: agg_u <- hi via csr_iu; t=1: agg_i <- hu via csr_ui
    {
        const long tot = (long)NN * 32;
        dim3 gg((unsigned)((tot + 255) / 256), 2);
        gather_mean_kernel<<<gg, 256>>>(hi, csr_iu, agg_u, hu, csr_ui, agg_i, off, cnt);
    }

    // layer 0 fused dual-GEMM + bias + LN + ReLU
    {
        GSide si = { agg_i, wl0ui_h, wl0ui_l, HD, 128, hi, wr0ui_h, wr0ui_l, HD, 128,
                     bl0_ui, g0_i, b0_i, hi1 };
        GSide su = { agg_u, wl0iu_h, wl0iu_l, HD, 128, hu, wr0iu_h, wr0iu_l, HD, 128,
                     bl0_iu, g0_u, b0_u, hu1 };
        mma_gemm<true, true, true><<<dim3(GM, 2), 256, SM>>>(si, su, NN);
    }

    // layer 1 combined GEMM pair: tmp = h1 @ [Wl1 | Wr1]
    float* tmp_u = agg_u;
    float* tmp_i = agg_i;
    {
        GSide su = { hu1, w1u_h, w1u_l, HD, 128, nullptr, nullptr, nullptr, 0, 0,
                     nullptr, nullptr, nullptr, tmp_u };
        GSide si = { hi1, w1i_h, w1i_l, HD, 128, nullptr, nullptr, nullptr, 0, 0,
                     nullptr, nullptr, nullptr, tmp_i };
        mma_gemm<false, false, false><<<dim3(GM, 2), 256, SM>>>(su, si, NN);
    }

    // fused layer-1 gather + final LN
    {
        FSide fu = { tmp_i, tmp_u, csr_iu, bl1_iu, g1_u, b1_u, out_u };
        FSide fi = { tmp_u, tmp_i, csr_ui, bl1_ui, g1_i, b1_i, out_i };
        dim3 gf((NN + 7) / 8, 2);
        final_fused_kernel<<<gf, 256>>>(fu, fi, off, cnt);
    }

    (void)n_in; (void)out_size; (void)in_sizes;
}